// round 14
// baseline (speedup 1.0000x reference)
#include <cuda_runtime.h>
#include <cuda_fp16.h>
#include <math.h>
#include <stdint.h>

// ---------------------------------------------------------------------------
// Problem constants
// ---------------------------------------------------------------------------
#define T_TOK   8192
#define HIDDEN  4096
#define NHEAD   16
#define HD      256
#define QKV_W   (3 * HIDDEN)     // 12288
#define BATCH   8
#define SEQ     1024
#define ROT_H   32               // rotary_dim/2

// Scratch (device globals: allocation-free rule)
__device__ float  g_qkv[(size_t)T_TOK * QKV_W];      // 8192 x 12288 fp32
__device__ __half g_attn16[(size_t)T_TOK * HIDDEN];  // attention out (fp16)
__device__ __half g_hid16[(size_t)T_TOK * HIDDEN];   // fp16 hidden
__device__ __half g_wq16 [(size_t)QKV_W * HIDDEN];   // fp16 w_qkv
__device__ __half g_wo16 [(size_t)HIDDEN * HIDDEN];  // fp16 w_o
// pre-split (RoPE-applied) q/k/v hi/lo halves, [T][16][256] each
__device__ __half g_qh[(size_t)T_TOK * HIDDEN];
__device__ __half g_ql[(size_t)T_TOK * HIDDEN];
__device__ __half g_kh[(size_t)T_TOK * HIDDEN];
__device__ __half g_kl[(size_t)T_TOK * HIDDEN];
__device__ __half g_vh[(size_t)T_TOK * HIDDEN];
__device__ __half g_vl[(size_t)T_TOK * HIDDEN];

// ---------------------------------------------------------------------------
// helpers
// ---------------------------------------------------------------------------
__device__ __forceinline__ uint32_t smem_u32(const void* p) {
    uint32_t a;
    asm("{ .reg .u64 t; cvta.to.shared.u64 t, %1; cvt.u32.u64 %0, t; }"
        : "=r"(a) : "l"(p));
    return a;
}

__device__ __forceinline__ void mma_f16(float* d, const unsigned* a, const unsigned* b) {
    asm volatile(
        "mma.sync.aligned.m16n8k16.row.col.f32.f16.f16.f32 "
        "{%0,%1,%2,%3}, {%4,%5,%6,%7}, {%8,%9}, {%0,%1,%2,%3};\n"
        : "+f"(d[0]), "+f"(d[1]), "+f"(d[2]), "+f"(d[3])
        : "r"(a[0]), "r"(a[1]), "r"(a[2]), "r"(a[3]),
          "r"(b[0]), "r"(b[1]));
}

__device__ __forceinline__ void ldsm4(unsigned* r, uint32_t addr) {
    asm volatile("ldmatrix.sync.aligned.m8n8.x4.shared.b16 {%0,%1,%2,%3}, [%4];"
        : "=r"(r[0]), "=r"(r[1]), "=r"(r[2]), "=r"(r[3]) : "r"(addr));
}
__device__ __forceinline__ void ldsm4t(unsigned* r, uint32_t addr) {
    asm volatile("ldmatrix.sync.aligned.m8n8.x4.trans.shared.b16 {%0,%1,%2,%3}, [%4];"
        : "=r"(r[0]), "=r"(r[1]), "=r"(r[2]), "=r"(r[3]) : "r"(addr));
}

__device__ __forceinline__ void cp16(uint32_t dst, const void* src) {
    asm volatile("cp.async.cg.shared.global [%0], [%1], 16;"
                 :: "r"(dst), "l"(src) : "memory");
}
#define CP_COMMIT()  asm volatile("cp.async.commit_group;" ::: "memory")
#define CP_WAITG2()  asm volatile("cp.async.wait_group 2;" ::: "memory")
#define CP_WAIT0()   asm volatile("cp.async.wait_group 0;" ::: "memory")

// split fp32x4 -> (hi fp16 x4, lo fp16 x4) and store 8B each
__device__ __forceinline__ void split_store(__half* bh, __half* bl, float4 v) {
    __half2 h0 = __floats2half2_rn(v.x, v.y);
    __half2 h1 = __floats2half2_rn(v.z, v.w);
    __half2 l0 = __floats2half2_rn(v.x - __low2float(h0), v.y - __high2float(h0));
    __half2 l1 = __floats2half2_rn(v.z - __low2float(h1), v.w - __high2float(h1));
    *(__half2*)(bh)     = h0;  *(__half2*)(bh + 2) = h1;
    *(__half2*)(bl)     = l0;  *(__half2*)(bl + 2) = l1;
}

// RoPE rotate a float4 at rotary chunk c4 (<16); base = &x[c4*4], partner +-32
__device__ __forceinline__ float4 rope_rot(
    const float* base, int c4, int t,
    const float* __restrict__ cosp, const float* __restrict__ sinp, float4 v)
{
    if (c4 < 8) {
        float4 x2 = *(const float4*)(base + 32);
        float4 cc = *(const float4*)(cosp + (size_t)t * ROT_H + c4 * 4);
        float4 ss = *(const float4*)(sinp + (size_t)t * ROT_H + c4 * 4);
        v.x = v.x * cc.x - x2.x * ss.x;
        v.y = v.y * cc.y - x2.y * ss.y;
        v.z = v.z * cc.z - x2.z * ss.z;
        v.w = v.w * cc.w - x2.w * ss.w;
    } else {
        float4 x1 = *(const float4*)(base - 32);
        int d4 = (c4 - 8) * 4;
        float4 cc = *(const float4*)(cosp + (size_t)t * ROT_H + d4);
        float4 ss = *(const float4*)(sinp + (size_t)t * ROT_H + d4);
        v.x = v.x * cc.x + x1.x * ss.x;
        v.y = v.y * cc.y + x1.y * ss.y;
        v.z = v.z * cc.z + x1.z * ss.z;
        v.w = v.w * cc.w + x1.w * ss.w;
    }
    return v;
}

// ---------------------------------------------------------------------------
// fp32 -> fp16 conversion pre-pass (rn): one launch covers hidden,w_qkv,w_o
// ---------------------------------------------------------------------------
#define F2H_N0 ((size_t)T_TOK * HIDDEN / 4)
#define F2H_N1 ((size_t)QKV_W * HIDDEN / 4)
#define F2H_N2 ((size_t)HIDDEN * HIDDEN / 4)

__global__ __launch_bounds__(256) void f2h_all(
    const float* __restrict__ s0, __half* __restrict__ d0,
    const float* __restrict__ s1, __half* __restrict__ d1,
    const float* __restrict__ s2, __half* __restrict__ d2)
{
    size_t i = (size_t)blockIdx.x * 256 + threadIdx.x;
    const float* src; __half* dst;
    if (i < F2H_N0) { src = s0; dst = d0; }
    else if (i < F2H_N0 + F2H_N1) { i -= F2H_N0; src = s1; dst = d1; }
    else { i -= F2H_N0 + F2H_N1; src = s2; dst = d2; }
    float4 v = *(const float4*)(src + i * 4);
    *(__half2*)(dst + i * 4)     = __floats2half2_rn(v.x, v.y);
    *(__half2*)(dst + i * 4 + 2) = __floats2half2_rn(v.z, v.w);
}

// ---------------------------------------------------------------------------
// prep: RoPE (q,k) + hi/lo split of q,k,v into persistent fp16 arrays.
// One thread per (t, h, c4) float4. Replaces rope_kernel; math identical to
// rope(fp32) followed by split — bit-identical downstream values.
// ---------------------------------------------------------------------------
__global__ __launch_bounds__(256) void prep_kernel(
    const float* __restrict__ qkv,
    const float* __restrict__ cosp, const float* __restrict__ sinp,
    __half* __restrict__ qh, __half* __restrict__ ql,
    __half* __restrict__ kh, __half* __restrict__ kl,
    __half* __restrict__ vh, __half* __restrict__ vl)
{
    int idx = blockIdx.x * 256 + threadIdx.x;   // over T*16*64
    int c4 = idx & 63;
    int h  = (idx >> 6) & 15;
    int t  = idx >> 10;
    const float* qb = qkv + (size_t)t * QKV_W + h * HD + c4 * 4;
    float4 qv = *(const float4*)qb;
    float4 kv = *(const float4*)(qb + HIDDEN);
    float4 vv = *(const float4*)(qb + 2 * HIDDEN);
    if (c4 < 16) {
        qv = rope_rot(qb, c4, t, cosp, sinp, qv);
        kv = rope_rot(qb + HIDDEN, c4, t, cosp, sinp, kv);
    }
    size_t o = (size_t)t * HIDDEN + h * HD + c4 * 4;
    split_store(qh + o, ql + o, qv);
    split_store(kh + o, kl + o, kv);
    split_store(vh + o, vl + o, vv);
}

// ---------------------------------------------------------------------------
// fp16 mma.sync GEMM (NT) — R7 byte-identical (empirically optimal config).
// ---------------------------------------------------------------------------
#define GTILE_M   128
#define GTILE_N   128
#define KTILE     32
#define ROW_B     80
#define A_ST_B    (128 * ROW_B)            // 10240 B
#define STAGE_B   (2 * A_ST_B)             // 20480 B
#define NSTG      4
#define GEMM_SMEM (NSTG * STAGE_B)         // 81920 B

__global__ __launch_bounds__(128, 2) void gemm_h(
    const __half* __restrict__ A, const __half* __restrict__ B,
    float* __restrict__ C, int M, int N, int K)
{
    extern __shared__ __align__(128) char smc[];
    const uint32_t sb = smem_u32(smc);

    const int tid  = threadIdx.x;
    const int lane = tid & 31;
    const int wid  = tid >> 5;
    const int wm   = wid >> 1;
    const int wn   = wid & 1;

    const int Nb = gridDim.x;
    const int Mb = gridDim.y;
    int linear = blockIdx.y * Nb + blockIdx.x;
    int group  = linear / (Nb * 8);
    int rem    = linear - group * (Nb * 8);
    int mstart = group * 8;
    int mspan  = Mb - mstart; if (mspan > 8) mspan = 8;
    int mb_id  = mstart + rem % mspan;
    int nb_id  = rem / mspan;
    const int m0 = mb_id * GTILE_M;
    const int n0 = nb_id * GTILE_N;

    const __half* srcA[4];  uint32_t dstA[4];
    const __half* srcB[4];  uint32_t dstB[4];
    #pragma unroll
    for (int i = 0; i < 4; i++) {
        int idx = tid + 128 * i;
        int row = idx >> 2, c = idx & 3;
        srcA[i] = A + (size_t)(m0 + row) * K + c * 8;
        dstA[i] = (uint32_t)(row * ROW_B + c * 16);
        srcB[i] = B + (size_t)(n0 + row) * K + c * 8;
        dstB[i] = (uint32_t)(A_ST_B + row * ROW_B + c * 16);
    }

    const int NT = K >> 5;

    #pragma unroll
    for (int s = 0; s < 3; s++) {
        const uint32_t st = sb + s * STAGE_B;
        #pragma unroll
        for (int i = 0; i < 4; i++) cp16(st + dstA[i], srcA[i] + s * KTILE);
        #pragma unroll
        for (int i = 0; i < 4; i++) cp16(st + dstB[i], srcB[i] + s * KTILE);
        CP_COMMIT();
    }

    float acc[4][8][4];
    #pragma unroll
    for (int f = 0; f < 4; f++)
        #pragma unroll
        for (int g = 0; g < 8; g++)
            #pragma unroll
            for (int r = 0; r < 4; r++) acc[f][g][r] = 0.f;

    const uint32_t aLane = (uint32_t)((wm * 64 + (lane & 15)) * ROW_B + ((lane >> 4) << 4));
    const uint32_t bLane = (uint32_t)(A_ST_B +
        (wn * 64 + ((lane >> 4) << 3) + (lane & 7)) * ROW_B + (((lane >> 3) & 1) << 4));

    for (int kt = 0; kt < NT; kt++) {
        CP_WAITG2();
        __syncthreads();

        if (kt + 3 < NT) {
            const uint32_t st = sb + ((kt + 3) % NSTG) * STAGE_B;
            const int ko = (kt + 3) * KTILE;
            #pragma unroll
            for (int i = 0; i < 4; i++) cp16(st + dstA[i], srcA[i] + ko);
            #pragma unroll
            for (int i = 0; i < 4; i++) cp16(st + dstB[i], srcB[i] + ko);
        }
        CP_COMMIT();

        const uint32_t stb = sb + (kt % NSTG) * STAGE_B;
        #pragma unroll
        for (int s = 0; s < 2; s++) {
            unsigned af[4][4], bf[4][4];
            #pragma unroll
            for (int f = 0; f < 4; f++)
                ldsm4(af[f], stb + aLane + f * (16 * ROW_B) + s * 32);
            #pragma unroll
            for (int g2 = 0; g2 < 4; g2++)
                ldsm4(bf[g2], stb + bLane + g2 * (16 * ROW_B) + s * 32);
            #pragma unroll
            for (int f = 0; f < 4; f++)
                #pragma unroll
                for (int g = 0; g < 8; g++)
                    mma_f16(acc[f][g], af[f], &bf[g >> 1][(g & 1) * 2]);
        }
    }

    const int r = lane >> 2;
    const int c = lane & 3;
    #pragma unroll
    for (int f = 0; f < 4; f++) {
        int row = m0 + wm * 64 + f * 16 + r;
        #pragma unroll
        for (int g = 0; g < 8; g++) {
            int col = n0 + wn * 64 + g * 8 + c * 2;
            float* cp = C + (size_t)row * N + col;
            *(float2*)cp = make_float2(acc[f][g][0], acc[f][g][1]);
            *(float2*)(cp + (size_t)8 * N) = make_float2(acc[f][g][2], acc[f][g][3]);
        }
    }
}

// ---------------------------------------------------------------------------
// fp16 3-pass compensated flash attention (causal). R7 mainloop; loaders are
// now pure cp.async from the pre-split fp16 arrays (no per-iter split work).
// ---------------------------------------------------------------------------
#define AQ 64
#define AKT 32
#define H_QH 0
#define H_QL 16384
#define H_KH 32768
#define H_KL 40960
#define H_VH 49152
#define H_VL 57344
#define H_PH 65536
#define H_PL 69632
#define F_M  36864
#define F_L  36928
#define F_PM 36992
#define F_PS 37120
#define ATT_SMEM  149504

__global__ __launch_bounds__(256, 1) void attn_h(
    const __half* __restrict__ qhg, const __half* __restrict__ qlg,
    const __half* __restrict__ khg, const __half* __restrict__ klg,
    const __half* __restrict__ vhg, const __half* __restrict__ vlg,
    __half* __restrict__ outp)
{
    extern __shared__ char sm[];
    __half* hp = (__half*)sm;
    float*  fpm = (float*)sm;
    const uint32_t sb = smem_u32(sm);

    const int tid = threadIdx.x, lane = tid & 31, w = tid >> 5;
    const int qt = 15 - blockIdx.x;
    const int bh = blockIdx.y;
    const int b = bh >> 4, h = bh & 15;
    const int t0 = b * SEQ + qt * AQ;
    const int wq = w & 3, wk = w >> 2;
    const int cL = lane & 3;
    const int rL = lane >> 2;
    const int rA = wq * 16 + rL;
    const int hoff = h * HD;

    // ---- q tile via cp.async (4096 chunks: qh then ql; arr = i>>3) ----
    #pragma unroll
    for (int i = 0; i < 16; i++) {
        const __half* srcb = (i < 8) ? qhg : qlg;
        const uint32_t hbase = (i < 8) ? H_QH : H_QL;
        int rem = tid + 256 * (i & 7);       // 0..2047
        int row = rem >> 5, ch = rem & 31;
        cp16(sb + 2 * (hbase + row * 256 + ((ch ^ (row & 7)) << 3)),
             srcb + (size_t)(t0 + row) * HIDDEN + hoff + ch * 8);
    }
    CP_COMMIT();
    if (tid < 64) { fpm[F_M + tid] = -INFINITY; fpm[F_L + tid] = 0.f; }

    float o[16][4];
    #pragma unroll
    for (int g = 0; g < 16; g++)
        #pragma unroll
        for (int r = 0; r < 4; r++) o[g][r] = 0.f;

    const int arow  = wq * 16 + (lane & 15);
    const int krow  = wk * 16 + ((lane & 7) | ((lane >> 4) << 3));
    const int vk    = lane & 15;
    const int acs   = lane >> 4;
    const int bcs   = (lane >> 3) & 1;
    const uint32_t qhB = sb + 2 * (H_QH + arow * 256);
    const uint32_t qlB = sb + 2 * (H_QL + arow * 256);
    const uint32_t khB = sb + 2 * (H_KH + krow * 256);
    const uint32_t klB = sb + 2 * (H_KL + krow * 256);
    const uint32_t phB = sb + 2 * (H_PH + arow * 64);
    const uint32_t plB = sb + 2 * (H_PL + arow * 64);
    const int arow7 = arow & 7, krow7 = krow & 7;

    const int ktmax = 2 * qt + 1;

    for (int kt = 0; kt <= ktmax; kt++) {
        __syncthreads();   // previous iteration's smem reads complete
        const int tk = b * SEQ + kt * AKT;
        // ---- k/v tiles via cp.async: 4096 chunks over kh,kl,vh,vl ----
        #pragma unroll
        for (int i = 0; i < 16; i++) {
            const __half* srcb = (i < 4) ? khg : (i < 8) ? klg : (i < 12) ? vhg : vlg;
            const uint32_t hbase = (i < 4) ? H_KH : (i < 8) ? H_KL : (i < 12) ? H_VH : H_VL;
            int rem = tid + 256 * (i & 3);   // 0..1023
            int row = rem >> 5, ch = rem & 31;
            cp16(sb + 2 * (hbase + row * 256 + ((ch ^ (row & 7)) << 3)),
                 srcb + (size_t)(tk + row) * HIDDEN + hoff + ch * 8);
        }
        CP_COMMIT();
        CP_WAIT0();
        __syncthreads();

        float sacc[2][4];
        #pragma unroll
        for (int g = 0; g < 2; g++)
            #pragma unroll
            for (int r = 0; r < 4; r++) sacc[g][r] = 0.f;

        #pragma unroll
        for (int s = 0; s < 16; s++) {
            unsigned ah[4], al2[4], bh2[4], bl2[4];
            uint32_t ac = (uint32_t)(((2 * s + acs) ^ arow7) << 4);
            uint32_t bc = (uint32_t)(((2 * s + bcs) ^ krow7) << 4);
            ldsm4(ah, qhB + ac);
            ldsm4(al2, qlB + ac);
            ldsm4(bh2, khB + bc);
            ldsm4(bl2, klB + bc);
            #pragma unroll
            for (int g = 0; g < 2; g++) {
                mma_f16(sacc[g], ah,  &bh2[2 * g]);
                mma_f16(sacc[g], al2, &bh2[2 * g]);
                mma_f16(sacc[g], ah,  &bl2[2 * g]);
            }
        }
        #pragma unroll
        for (int g = 0; g < 2; g++)
            #pragma unroll
            for (int r = 0; r < 4; r++) sacc[g][r] *= 0.0625f;

        if (kt >= 2 * qt) {
            #pragma unroll
            for (int g = 0; g < 2; g++)
                #pragma unroll
                for (int r = 0; r < 4; r++) {
                    int col = kt * AKT + wk * 16 + g * 8 + 2 * cL + (r & 1);
                    int row = qt * AQ + rA + 8 * (r >> 1);
                    if (col > row) sacc[g][r] = -1e30f;
                }
        }

        float mx0 = fmaxf(fmaxf(sacc[0][0], sacc[0][1]), fmaxf(sacc[1][0], sacc[1][1]));
        float mx1 = fmaxf(fmaxf(sacc[0][2], sacc[0][3]), fmaxf(sacc[1][2], sacc[1][3]));
        mx0 = fmaxf(mx0, __shfl_xor_sync(0xffffffffu, mx0, 1));
        mx0 = fmaxf(mx0, __shfl_xor_sync(0xffffffffu, mx0, 2));
        mx1 = fmaxf(mx1, __shfl_xor_sync(0xffffffffu, mx1, 1));
        mx1 = fmaxf(mx1, __shfl_xor_sync(0xffffffffu, mx1, 2));
        if (cL == 0) {
            fpm[F_PM + wk * 64 + rA]     = mx0;
            fpm[F_PM + wk * 64 + rA + 8] = mx1;
        }
        __syncthreads();

        float mo0 = fpm[F_M + rA], mo1 = fpm[F_M + rA + 8];
        float mn0 = fmaxf(mo0, fmaxf(fpm[F_PM + rA],     fpm[F_PM + 64 + rA]));
        float mn1 = fmaxf(mo1, fmaxf(fpm[F_PM + rA + 8], fpm[F_PM + 64 + rA + 8]));
        float al0 = __expf(mo0 - mn0), al1 = __expf(mo1 - mn1);

        float sum0 = 0.f, sum1 = 0.f;
        #pragma unroll
        for (int g = 0; g < 2; g++) {
            float p0 = __expf(sacc[g][0] - mn0);
            float p1 = __expf(sacc[g][1] - mn0);
            float p2 = __expf(sacc[g][2] - mn1);
            float p3 = __expf(sacc[g][3] - mn1);
            sum0 += p0 + p1; sum1 += p2 + p3;
            __half2 h01 = __floats2half2_rn(p0, p1);
            __half2 h23 = __floats2half2_rn(p2, p3);
            __half2 l01 = __floats2half2_rn(p0 - __low2float(h01), p1 - __high2float(h01));
            __half2 l23 = __floats2half2_rn(p2 - __low2float(h23), p3 - __high2float(h23));
            int pc = wk * 2 + g;
            uint32_t o0 = H_PH + rA * 64 + ((pc ^ (rA & 7)) << 3) + 2 * cL;
            uint32_t o1 = H_PH + (rA + 8) * 64 + ((pc ^ (rA & 7)) << 3) + 2 * cL;
            *(__half2*)&hp[o0] = h01;
            *(__half2*)&hp[o1] = h23;
            *(__half2*)&hp[o0 + (H_PL - H_PH)] = l01;
            *(__half2*)&hp[o1 + (H_PL - H_PH)] = l23;
        }
        sum0 += __shfl_xor_sync(0xffffffffu, sum0, 1);
        sum0 += __shfl_xor_sync(0xffffffffu, sum0, 2);
        sum1 += __shfl_xor_sync(0xffffffffu, sum1, 1);
        sum1 += __shfl_xor_sync(0xffffffffu, sum1, 2);
        if (cL == 0) {
            fpm[F_PS + wk * 64 + rA]     = sum0;
            fpm[F_PS + wk * 64 + rA + 8] = sum1;
        }
        #pragma unroll
        for (int g = 0; g < 16; g++) {
            o[g][0] *= al0; o[g][1] *= al0;
            o[g][2] *= al1; o[g][3] *= al1;
        }
        __syncthreads();

        if (wk == 0 && cL == 0) {
            fpm[F_M + rA]     = mn0;
            fpm[F_M + rA + 8] = mn1;
            fpm[F_L + rA]     = fpm[F_L + rA]     * al0 + fpm[F_PS + rA]     + fpm[F_PS + 64 + rA];
            fpm[F_L + rA + 8] = fpm[F_L + rA + 8] * al1 + fpm[F_PS + rA + 8] + fpm[F_PS + 64 + rA + 8];
        }

        // PV: s selects k16 half; v rows = s*16 + (lane&15)
        #pragma unroll
        for (int s = 0; s < 2; s++) {
            unsigned pa[4], pl4[4];
            uint32_t pc = (uint32_t)(((2 * s + acs) ^ arow7) << 4);
            ldsm4(pa, phB + pc);
            ldsm4(pl4, plB + pc);
            const uint32_t vrow = s * 16 + vk;
            const uint32_t vhBs = sb + 2 * (H_VH + vrow * 256);
            const uint32_t vlBs = sb + 2 * (H_VL + vrow * 256);
            const int vr7 = vrow & 7;
            #pragma unroll
            for (int G = 0; G < 8; G++) {
                unsigned vh4[4], vl4[4];
                uint32_t vc = (uint32_t)((((wk * 16 + 2 * G + acs)) ^ vr7) << 4);
                ldsm4t(vh4, vhBs + vc);
                ldsm4t(vl4, vlBs + vc);
                int gg = 2 * G;
                mma_f16(o[gg],     pa,  &vh4[0]);
                mma_f16(o[gg],     pl4, &vh4[0]);
                mma_f16(o[gg],     pa,  &vl4[0]);
                mma_f16(o[gg + 1], pa,  &vh4[2]);
                mma_f16(o[gg + 1], pl4, &vh4[2]);
                mma_f16(o[gg + 1], pa,  &vl4[2]);
            }
        }
    }

    __syncthreads();
    const float il0 = 1.0f / fpm[F_L + rA];
    const float il1 = 1.0f / fpm[F_L + rA + 8];
    #pragma unroll
    for (int g = 0; g < 16; g++) {
        int col = h * HD + wk * 128 + g * 8 + 2 * cL;
        *(__half2*)(outp + (size_t)(t0 + rA) * HIDDEN + col) =
            __floats2half2_rn(o[g][0] * il0, o[g][1] * il0);
        *(__half2*)(outp + (size_t)(t0 + rA + 8) * HIDDEN + col) =
            __floats2half2_rn(o[g][2] * il1, o[g][3] * il1);
    }
}

// ---------------------------------------------------------------------------
// launch
// ---------------------------------------------------------------------------
extern "C" void kernel_launch(void* const* d_in, const int* in_sizes, int n_in,
                              void* d_out, int out_size)
{
    const float* hidden = (const float*)d_in[0];
    const float* w_qkv  = (const float*)d_in[1];
    const float* w_o    = (const float*)d_in[2];
    const float* cosp   = (const float*)d_in[3];
    const float* sinp   = (const float*)d_in[4];
    // d_in[5..8] (caches, slots, batch_size) unused: cache write+gather is identity.

    float*  qkv;  cudaGetSymbolAddress((void**)&qkv,  g_qkv);
    __half* at16; cudaGetSymbolAddress((void**)&at16, g_attn16);
    __half* h16;  cudaGetSymbolAddress((void**)&h16,  g_hid16);
    __half* wq16; cudaGetSymbolAddress((void**)&wq16, g_wq16);
    __half* wo16; cudaGetSymbolAddress((void**)&wo16, g_wo16);
    __half *qh, *ql, *kh, *kl, *vh, *vl;
    cudaGetSymbolAddress((void**)&qh, g_qh);
    cudaGetSymbolAddress((void**)&ql, g_ql);
    cudaGetSymbolAddress((void**)&kh, g_kh);
    cudaGetSymbolAddress((void**)&kl, g_kl);
    cudaGetSymbolAddress((void**)&vh, g_vh);
    cudaGetSymbolAddress((void**)&vl, g_vl);

    cudaFuncSetAttribute(gemm_h, cudaFuncAttributeMaxDynamicSharedMemorySize, GEMM_SMEM);
    cudaFuncSetAttribute(attn_h, cudaFuncAttributeMaxDynamicSharedMemorySize, ATT_SMEM);

    // 0) fp16 conversion pre-pass (single launch, three segments)
    {
        size_t total = F2H_N0 + F2H_N1 + F2H_N2;
        f2h_all<<<(unsigned)((total + 255) / 256), 256>>>(
            hidden, h16, w_qkv, wq16, w_o, wo16);
    }
    // 1) qkv = hidden @ w_qkv^T
    {
        dim3 grid(QKV_W / GTILE_N, T_TOK / GTILE_M);   // (96, 64)
        gemm_h<<<grid, 128, GEMM_SMEM>>>(h16, wq16, qkv, T_TOK, QKV_W, HIDDEN);
    }
    // 2) RoPE + hi/lo split of q,k,v (single-touch)
    prep_kernel<<<(T_TOK * NHEAD * 64) / 256, 256>>>(qkv, cosp, sinp,
                                                     qh, ql, kh, kl, vh, vl);
    // 3) fp16 3-pass flash attention (cp.async loaders) -> fp16
    {
        dim3 grid(SEQ / AQ, BATCH * NHEAD);
        attn_h<<<grid, 256, ATT_SMEM>>>(qh, ql, kh, kl, vh, vl, at16);
    }
    // 4) out = attn @ w_o^T
    {
        dim3 grid(HIDDEN / GTILE_N, T_TOK / GTILE_M);  // (32, 64)
        gemm_h<<<grid, 128, GEMM_SMEM>>>(at16, wo16, (float*)d_out, T_TOK, HIDDEN, HIDDEN);
    }
}

// round 15
// speedup vs baseline: 1.0342x; 1.0342x over previous
#include <cuda_runtime.h>
#include <cuda_fp16.h>
#include <math.h>
#include <stdint.h>

// ---------------------------------------------------------------------------
// Problem constants
// ---------------------------------------------------------------------------
#define T_TOK   8192
#define HIDDEN  4096
#define NHEAD   16
#define HD      256
#define QKV_W   (3 * HIDDEN)     // 12288
#define BATCH   8
#define SEQ     1024
#define ROT_H   32               // rotary_dim/2

// Scratch (device globals: allocation-free rule)
__device__ float  g_qkv[(size_t)T_TOK * QKV_W];      // 8192 x 12288 fp32
__device__ __half g_attn16[(size_t)T_TOK * HIDDEN];  // attention out (fp16)
__device__ __half g_hid16[(size_t)T_TOK * HIDDEN];   // fp16 hidden
__device__ __half g_wq16 [(size_t)QKV_W * HIDDEN];   // fp16 w_qkv
__device__ __half g_wo16 [(size_t)HIDDEN * HIDDEN];  // fp16 w_o
// pre-split (RoPE-applied) q/k/v hi/lo halves, [T][16][256] each
__device__ __half g_qh[(size_t)T_TOK * HIDDEN];
__device__ __half g_ql[(size_t)T_TOK * HIDDEN];
__device__ __half g_kh[(size_t)T_TOK * HIDDEN];
__device__ __half g_kl[(size_t)T_TOK * HIDDEN];
__device__ __half g_vh[(size_t)T_TOK * HIDDEN];
__device__ __half g_vl[(size_t)T_TOK * HIDDEN];

// ---------------------------------------------------------------------------
// helpers
// ---------------------------------------------------------------------------
__device__ __forceinline__ uint32_t smem_u32(const void* p) {
    uint32_t a;
    asm("{ .reg .u64 t; cvta.to.shared.u64 t, %1; cvt.u32.u64 %0, t; }"
        : "=r"(a) : "l"(p));
    return a;
}

__device__ __forceinline__ void mma_f16(float* d, const unsigned* a, const unsigned* b) {
    asm volatile(
        "mma.sync.aligned.m16n8k16.row.col.f32.f16.f16.f32 "
        "{%0,%1,%2,%3}, {%4,%5,%6,%7}, {%8,%9}, {%0,%1,%2,%3};\n"
        : "+f"(d[0]), "+f"(d[1]), "+f"(d[2]), "+f"(d[3])
        : "r"(a[0]), "r"(a[1]), "r"(a[2]), "r"(a[3]),
          "r"(b[0]), "r"(b[1]));
}

__device__ __forceinline__ void ldsm4(unsigned* r, uint32_t addr) {
    asm volatile("ldmatrix.sync.aligned.m8n8.x4.shared.b16 {%0,%1,%2,%3}, [%4];"
        : "=r"(r[0]), "=r"(r[1]), "=r"(r[2]), "=r"(r[3]) : "r"(addr));
}
__device__ __forceinline__ void ldsm4t(unsigned* r, uint32_t addr) {
    asm volatile("ldmatrix.sync.aligned.m8n8.x4.trans.shared.b16 {%0,%1,%2,%3}, [%4];"
        : "=r"(r[0]), "=r"(r[1]), "=r"(r[2]), "=r"(r[3]) : "r"(addr));
}

__device__ __forceinline__ void cp16(uint32_t dst, const void* src) {
    asm volatile("cp.async.cg.shared.global [%0], [%1], 16;"
                 :: "r"(dst), "l"(src) : "memory");
}
#define CP_COMMIT()  asm volatile("cp.async.commit_group;" ::: "memory")
#define CP_WAITG2()  asm volatile("cp.async.wait_group 2;" ::: "memory")
#define CP_WAIT0()   asm volatile("cp.async.wait_group 0;" ::: "memory")

// split fp32x4 -> (hi fp16 x4, lo fp16 x4) and store 8B each
__device__ __forceinline__ void split_store(__half* bh, __half* bl, float4 v) {
    __half2 h0 = __floats2half2_rn(v.x, v.y);
    __half2 h1 = __floats2half2_rn(v.z, v.w);
    __half2 l0 = __floats2half2_rn(v.x - __low2float(h0), v.y - __high2float(h0));
    __half2 l1 = __floats2half2_rn(v.z - __low2float(h1), v.w - __high2float(h1));
    *(__half2*)(bh)     = h0;  *(__half2*)(bh + 2) = h1;
    *(__half2*)(bl)     = l0;  *(__half2*)(bl + 2) = l1;
}

// RoPE rotate a float4 at rotary chunk c4 (<16); base = &x[c4*4], partner +-32
__device__ __forceinline__ float4 rope_rot(
    const float* base, int c4, int t,
    const float* __restrict__ cosp, const float* __restrict__ sinp, float4 v)
{
    if (c4 < 8) {
        float4 x2 = *(const float4*)(base + 32);
        float4 cc = *(const float4*)(cosp + (size_t)t * ROT_H + c4 * 4);
        float4 ss = *(const float4*)(sinp + (size_t)t * ROT_H + c4 * 4);
        v.x = v.x * cc.x - x2.x * ss.x;
        v.y = v.y * cc.y - x2.y * ss.y;
        v.z = v.z * cc.z - x2.z * ss.z;
        v.w = v.w * cc.w - x2.w * ss.w;
    } else {
        float4 x1 = *(const float4*)(base - 32);
        int d4 = (c4 - 8) * 4;
        float4 cc = *(const float4*)(cosp + (size_t)t * ROT_H + d4);
        float4 ss = *(const float4*)(sinp + (size_t)t * ROT_H + d4);
        v.x = v.x * cc.x + x1.x * ss.x;
        v.y = v.y * cc.y + x1.y * ss.y;
        v.z = v.z * cc.z + x1.z * ss.z;
        v.w = v.w * cc.w + x1.w * ss.w;
    }
    return v;
}

// ---------------------------------------------------------------------------
// fp32 -> fp16 conversion pre-pass (rn): one launch covers hidden,w_qkv,w_o
// ---------------------------------------------------------------------------
#define F2H_N0 ((size_t)T_TOK * HIDDEN / 4)
#define F2H_N1 ((size_t)QKV_W * HIDDEN / 4)
#define F2H_N2 ((size_t)HIDDEN * HIDDEN / 4)

__global__ __launch_bounds__(256) void f2h_all(
    const float* __restrict__ s0, __half* __restrict__ d0,
    const float* __restrict__ s1, __half* __restrict__ d1,
    const float* __restrict__ s2, __half* __restrict__ d2)
{
    size_t i = (size_t)blockIdx.x * 256 + threadIdx.x;
    const float* src; __half* dst;
    if (i < F2H_N0) { src = s0; dst = d0; }
    else if (i < F2H_N0 + F2H_N1) { i -= F2H_N0; src = s1; dst = d1; }
    else { i -= F2H_N0 + F2H_N1; src = s2; dst = d2; }
    float4 v = *(const float4*)(src + i * 4);
    *(__half2*)(dst + i * 4)     = __floats2half2_rn(v.x, v.y);
    *(__half2*)(dst + i * 4 + 2) = __floats2half2_rn(v.z, v.w);
}

// ---------------------------------------------------------------------------
// prep: RoPE (q,k) + hi/lo split of q,k,v into persistent fp16 arrays.
// ---------------------------------------------------------------------------
__global__ __launch_bounds__(256) void prep_kernel(
    const float* __restrict__ qkv,
    const float* __restrict__ cosp, const float* __restrict__ sinp,
    __half* __restrict__ qh, __half* __restrict__ ql,
    __half* __restrict__ kh, __half* __restrict__ kl,
    __half* __restrict__ vh, __half* __restrict__ vl)
{
    int idx = blockIdx.x * 256 + threadIdx.x;   // over T*16*64
    int c4 = idx & 63;
    int h  = (idx >> 6) & 15;
    int t  = idx >> 10;
    const float* qb = qkv + (size_t)t * QKV_W + h * HD + c4 * 4;
    float4 qv = *(const float4*)qb;
    float4 kv = *(const float4*)(qb + HIDDEN);
    float4 vv = *(const float4*)(qb + 2 * HIDDEN);
    if (c4 < 16) {
        qv = rope_rot(qb, c4, t, cosp, sinp, qv);
        kv = rope_rot(qb + HIDDEN, c4, t, cosp, sinp, kv);
    }
    size_t o = (size_t)t * HIDDEN + h * HD + c4 * 4;
    split_store(qh + o, ql + o, qv);
    split_store(kh + o, kl + o, kv);
    split_store(vh + o, vl + o, vv);
}

// ---------------------------------------------------------------------------
// fp16 mma.sync GEMM (NT) — R7 byte-identical (empirically optimal config).
// ---------------------------------------------------------------------------
#define GTILE_M   128
#define GTILE_N   128
#define KTILE     32
#define ROW_B     80
#define A_ST_B    (128 * ROW_B)            // 10240 B
#define STAGE_B   (2 * A_ST_B)             // 20480 B
#define NSTG      4
#define GEMM_SMEM (NSTG * STAGE_B)         // 81920 B

__global__ __launch_bounds__(128, 2) void gemm_h(
    const __half* __restrict__ A, const __half* __restrict__ B,
    float* __restrict__ C, int M, int N, int K)
{
    extern __shared__ __align__(128) char smc[];
    const uint32_t sb = smem_u32(smc);

    const int tid  = threadIdx.x;
    const int lane = tid & 31;
    const int wid  = tid >> 5;
    const int wm   = wid >> 1;
    const int wn   = wid & 1;

    const int Nb = gridDim.x;
    const int Mb = gridDim.y;
    int linear = blockIdx.y * Nb + blockIdx.x;
    int group  = linear / (Nb * 8);
    int rem    = linear - group * (Nb * 8);
    int mstart = group * 8;
    int mspan  = Mb - mstart; if (mspan > 8) mspan = 8;
    int mb_id  = mstart + rem % mspan;
    int nb_id  = rem / mspan;
    const int m0 = mb_id * GTILE_M;
    const int n0 = nb_id * GTILE_N;

    const __half* srcA[4];  uint32_t dstA[4];
    const __half* srcB[4];  uint32_t dstB[4];
    #pragma unroll
    for (int i = 0; i < 4; i++) {
        int idx = tid + 128 * i;
        int row = idx >> 2, c = idx & 3;
        srcA[i] = A + (size_t)(m0 + row) * K + c * 8;
        dstA[i] = (uint32_t)(row * ROW_B + c * 16);
        srcB[i] = B + (size_t)(n0 + row) * K + c * 8;
        dstB[i] = (uint32_t)(A_ST_B + row * ROW_B + c * 16);
    }

    const int NT = K >> 5;

    #pragma unroll
    for (int s = 0; s < 3; s++) {
        const uint32_t st = sb + s * STAGE_B;
        #pragma unroll
        for (int i = 0; i < 4; i++) cp16(st + dstA[i], srcA[i] + s * KTILE);
        #pragma unroll
        for (int i = 0; i < 4; i++) cp16(st + dstB[i], srcB[i] + s * KTILE);
        CP_COMMIT();
    }

    float acc[4][8][4];
    #pragma unroll
    for (int f = 0; f < 4; f++)
        #pragma unroll
        for (int g = 0; g < 8; g++)
            #pragma unroll
            for (int r = 0; r < 4; r++) acc[f][g][r] = 0.f;

    const uint32_t aLane = (uint32_t)((wm * 64 + (lane & 15)) * ROW_B + ((lane >> 4) << 4));
    const uint32_t bLane = (uint32_t)(A_ST_B +
        (wn * 64 + ((lane >> 4) << 3) + (lane & 7)) * ROW_B + (((lane >> 3) & 1) << 4));

    for (int kt = 0; kt < NT; kt++) {
        CP_WAITG2();
        __syncthreads();

        if (kt + 3 < NT) {
            const uint32_t st = sb + ((kt + 3) % NSTG) * STAGE_B;
            const int ko = (kt + 3) * KTILE;
            #pragma unroll
            for (int i = 0; i < 4; i++) cp16(st + dstA[i], srcA[i] + ko);
            #pragma unroll
            for (int i = 0; i < 4; i++) cp16(st + dstB[i], srcB[i] + ko);
        }
        CP_COMMIT();

        const uint32_t stb = sb + (kt % NSTG) * STAGE_B;
        #pragma unroll
        for (int s = 0; s < 2; s++) {
            unsigned af[4][4], bf[4][4];
            #pragma unroll
            for (int f = 0; f < 4; f++)
                ldsm4(af[f], stb + aLane + f * (16 * ROW_B) + s * 32);
            #pragma unroll
            for (int g2 = 0; g2 < 4; g2++)
                ldsm4(bf[g2], stb + bLane + g2 * (16 * ROW_B) + s * 32);
            #pragma unroll
            for (int f = 0; f < 4; f++)
                #pragma unroll
                for (int g = 0; g < 8; g++)
                    mma_f16(acc[f][g], af[f], &bf[g >> 1][(g & 1) * 2]);
        }
    }

    const int r = lane >> 2;
    const int c = lane & 3;
    #pragma unroll
    for (int f = 0; f < 4; f++) {
        int row = m0 + wm * 64 + f * 16 + r;
        #pragma unroll
        for (int g = 0; g < 8; g++) {
            int col = n0 + wn * 64 + g * 8 + c * 2;
            float* cp = C + (size_t)row * N + col;
            *(float2*)cp = make_float2(acc[f][g][0], acc[f][g][1]);
            *(float2*)(cp + (size_t)8 * N) = make_float2(acc[f][g][2], acc[f][g][3]);
        }
    }
}

// ---------------------------------------------------------------------------
// fp16 3-pass compensated flash attention (causal). R7 mainloop; cp.async
// loaders from pre-split fp16 arrays; k/v smem tiles DOUBLE-BUFFERED so the
// tile kt+1 gmem load overlaps tile kt compute (latency fully hidden).
// ---------------------------------------------------------------------------
#define AQ 64
#define AKT 32
// smem half-offsets
#define H_QH 0
#define H_QL 16384
#define H_KH 32768               // stage 0; stage 1 = +KV_STG_H
#define H_KL 40960
#define H_VH 49152
#define H_VL 57344
#define KV_STG_H 32768           // halves per k/v stage
#define KV_STG_B 65536           // bytes per k/v stage
#define H_PH 98304
#define H_PL 102400
// stats in FLOAT units (half index 106496 -> float 53248)
#define F_M  53248
#define F_L  53312
#define F_PM 53376
#define F_PS 53504
#define ATT_SMEM  214528

__global__ __launch_bounds__(256, 1) void attn_h(
    const __half* __restrict__ qhg, const __half* __restrict__ qlg,
    const __half* __restrict__ khg, const __half* __restrict__ klg,
    const __half* __restrict__ vhg, const __half* __restrict__ vlg,
    __half* __restrict__ outp)
{
    extern __shared__ char sm[];
    __half* hp = (__half*)sm;
    float*  fpm = (float*)sm;
    const uint32_t sb = smem_u32(sm);

    const int tid = threadIdx.x, lane = tid & 31, w = tid >> 5;
    const int qt = 15 - blockIdx.x;
    const int bh = blockIdx.y;
    const int b = bh >> 4, h = bh & 15;
    const int t0 = b * SEQ + qt * AQ;
    const int wq = w & 3, wk = w >> 2;
    const int cL = lane & 3;
    const int rL = lane >> 2;
    const int rA = wq * 16 + rL;
    const int hoff = h * HD;
    const int ktmax = 2 * qt + 1;

    // ---- q tile via cp.async ----
    #pragma unroll
    for (int i = 0; i < 16; i++) {
        const __half* srcb = (i < 8) ? qhg : qlg;
        const uint32_t hbase = (i < 8) ? H_QH : H_QL;
        int rem = tid + 256 * (i & 7);
        int row = rem >> 5, ch = rem & 31;
        cp16(sb + 2 * (hbase + row * 256 + ((ch ^ (row & 7)) << 3)),
             srcb + (size_t)(t0 + row) * HIDDEN + hoff + ch * 8);
    }
    CP_COMMIT();
    // ---- k/v tile 0 into stage 0 ----
    {
        const int tk = b * SEQ;
        #pragma unroll
        for (int i = 0; i < 16; i++) {
            const __half* srcb = (i < 4) ? khg : (i < 8) ? klg : (i < 12) ? vhg : vlg;
            const uint32_t hbase = (i < 4) ? H_KH : (i < 8) ? H_KL : (i < 12) ? H_VH : H_VL;
            int rem = tid + 256 * (i & 3);
            int row = rem >> 5, ch = rem & 31;
            cp16(sb + 2 * (hbase + row * 256 + ((ch ^ (row & 7)) << 3)),
                 srcb + (size_t)(tk + row) * HIDDEN + hoff + ch * 8);
        }
        CP_COMMIT();
    }
    if (tid < 64) { fpm[F_M + tid] = -INFINITY; fpm[F_L + tid] = 0.f; }

    float o[16][4];
    #pragma unroll
    for (int g = 0; g < 16; g++)
        #pragma unroll
        for (int r = 0; r < 4; r++) o[g][r] = 0.f;

    const int arow  = wq * 16 + (lane & 15);
    const int krow  = wk * 16 + ((lane & 7) | ((lane >> 4) << 3));
    const int vk    = lane & 15;
    const int acs   = lane >> 4;
    const int bcs   = (lane >> 3) & 1;
    const uint32_t qhB = sb + 2 * (H_QH + arow * 256);
    const uint32_t qlB = sb + 2 * (H_QL + arow * 256);
    const uint32_t khB = sb + 2 * (H_KH + krow * 256);
    const uint32_t klB = sb + 2 * (H_KL + krow * 256);
    const uint32_t phB = sb + 2 * (H_PH + arow * 64);
    const uint32_t plB = sb + 2 * (H_PL + arow * 64);
    const int arow7 = arow & 7, krow7 = krow & 7;

    for (int kt = 0; kt <= ktmax; kt++) {
        CP_WAIT0();        // tile kt resident (q too, at kt=0)
        __syncthreads();   // all warps done with the other stage; data visible

        // prefetch tile kt+1 into the other stage (overlaps compute below)
        if (kt < ktmax) {
            const int tk = b * SEQ + (kt + 1) * AKT;
            const uint32_t stg = ((kt + 1) & 1) ? (uint32_t)KV_STG_B : 0u;
            #pragma unroll
            for (int i = 0; i < 16; i++) {
                const __half* srcb = (i < 4) ? khg : (i < 8) ? klg : (i < 12) ? vhg : vlg;
                const uint32_t hbase = (i < 4) ? H_KH : (i < 8) ? H_KL : (i < 12) ? H_VH : H_VL;
                int rem = tid + 256 * (i & 3);
                int row = rem >> 5, ch = rem & 31;
                cp16(stg + sb + 2 * (hbase + row * 256 + ((ch ^ (row & 7)) << 3)),
                     srcb + (size_t)(tk + row) * HIDDEN + hoff + ch * 8);
            }
            CP_COMMIT();
        }

        const uint32_t stgc = (kt & 1) ? (uint32_t)KV_STG_B : 0u;

        float sacc[2][4];
        #pragma unroll
        for (int g = 0; g < 2; g++)
            #pragma unroll
            for (int r = 0; r < 4; r++) sacc[g][r] = 0.f;

        #pragma unroll
        for (int s = 0; s < 16; s++) {
            unsigned ah[4], al2[4], bh2[4], bl2[4];
            uint32_t ac = (uint32_t)(((2 * s + acs) ^ arow7) << 4);
            uint32_t bc = (uint32_t)(((2 * s + bcs) ^ krow7) << 4);
            ldsm4(ah, qhB + ac);
            ldsm4(al2, qlB + ac);
            ldsm4(bh2, khB + stgc + bc);
            ldsm4(bl2, klB + stgc + bc);
            #pragma unroll
            for (int g = 0; g < 2; g++) {
                mma_f16(sacc[g], ah,  &bh2[2 * g]);
                mma_f16(sacc[g], al2, &bh2[2 * g]);
                mma_f16(sacc[g], ah,  &bl2[2 * g]);
            }
        }
        #pragma unroll
        for (int g = 0; g < 2; g++)
            #pragma unroll
            for (int r = 0; r < 4; r++) sacc[g][r] *= 0.0625f;

        if (kt >= 2 * qt) {
            #pragma unroll
            for (int g = 0; g < 2; g++)
                #pragma unroll
                for (int r = 0; r < 4; r++) {
                    int col = kt * AKT + wk * 16 + g * 8 + 2 * cL + (r & 1);
                    int row = qt * AQ + rA + 8 * (r >> 1);
                    if (col > row) sacc[g][r] = -1e30f;
                }
        }

        float mx0 = fmaxf(fmaxf(sacc[0][0], sacc[0][1]), fmaxf(sacc[1][0], sacc[1][1]));
        float mx1 = fmaxf(fmaxf(sacc[0][2], sacc[0][3]), fmaxf(sacc[1][2], sacc[1][3]));
        mx0 = fmaxf(mx0, __shfl_xor_sync(0xffffffffu, mx0, 1));
        mx0 = fmaxf(mx0, __shfl_xor_sync(0xffffffffu, mx0, 2));
        mx1 = fmaxf(mx1, __shfl_xor_sync(0xffffffffu, mx1, 1));
        mx1 = fmaxf(mx1, __shfl_xor_sync(0xffffffffu, mx1, 2));
        if (cL == 0) {
            fpm[F_PM + wk * 64 + rA]     = mx0;
            fpm[F_PM + wk * 64 + rA + 8] = mx1;
        }
        __syncthreads();

        float mo0 = fpm[F_M + rA], mo1 = fpm[F_M + rA + 8];
        float mn0 = fmaxf(mo0, fmaxf(fpm[F_PM + rA],     fpm[F_PM + 64 + rA]));
        float mn1 = fmaxf(mo1, fmaxf(fpm[F_PM + rA + 8], fpm[F_PM + 64 + rA + 8]));
        float al0 = __expf(mo0 - mn0), al1 = __expf(mo1 - mn1);

        float sum0 = 0.f, sum1 = 0.f;
        #pragma unroll
        for (int g = 0; g < 2; g++) {
            float p0 = __expf(sacc[g][0] - mn0);
            float p1 = __expf(sacc[g][1] - mn0);
            float p2 = __expf(sacc[g][2] - mn1);
            float p3 = __expf(sacc[g][3] - mn1);
            sum0 += p0 + p1; sum1 += p2 + p3;
            __half2 h01 = __floats2half2_rn(p0, p1);
            __half2 h23 = __floats2half2_rn(p2, p3);
            __half2 l01 = __floats2half2_rn(p0 - __low2float(h01), p1 - __high2float(h01));
            __half2 l23 = __floats2half2_rn(p2 - __low2float(h23), p3 - __high2float(h23));
            int pc = wk * 2 + g;
            uint32_t o0 = H_PH + rA * 64 + ((pc ^ (rA & 7)) << 3) + 2 * cL;
            uint32_t o1 = H_PH + (rA + 8) * 64 + ((pc ^ (rA & 7)) << 3) + 2 * cL;
            *(__half2*)&hp[o0] = h01;
            *(__half2*)&hp[o1] = h23;
            *(__half2*)&hp[o0 + (H_PL - H_PH)] = l01;
            *(__half2*)&hp[o1 + (H_PL - H_PH)] = l23;
        }
        sum0 += __shfl_xor_sync(0xffffffffu, sum0, 1);
        sum0 += __shfl_xor_sync(0xffffffffu, sum0, 2);
        sum1 += __shfl_xor_sync(0xffffffffu, sum1, 1);
        sum1 += __shfl_xor_sync(0xffffffffu, sum1, 2);
        if (cL == 0) {
            fpm[F_PS + wk * 64 + rA]     = sum0;
            fpm[F_PS + wk * 64 + rA + 8] = sum1;
        }
        #pragma unroll
        for (int g = 0; g < 16; g++) {
            o[g][0] *= al0; o[g][1] *= al0;
            o[g][2] *= al1; o[g][3] *= al1;
        }
        __syncthreads();

        if (wk == 0 && cL == 0) {
            fpm[F_M + rA]     = mn0;
            fpm[F_M + rA + 8] = mn1;
            fpm[F_L + rA]     = fpm[F_L + rA]     * al0 + fpm[F_PS + rA]     + fpm[F_PS + 64 + rA];
            fpm[F_L + rA + 8] = fpm[F_L + rA + 8] * al1 + fpm[F_PS + rA + 8] + fpm[F_PS + 64 + rA + 8];
        }

        // PV: s selects k16 half; v rows = s*16 + (lane&15)
        #pragma unroll
        for (int s = 0; s < 2; s++) {
            unsigned pa[4], pl4[4];
            uint32_t pc = (uint32_t)(((2 * s + acs) ^ arow7) << 4);
            ldsm4(pa, phB + pc);
            ldsm4(pl4, plB + pc);
            const uint32_t vrow = s * 16 + vk;
            const uint32_t vhBs = sb + stgc + 2 * (H_VH + vrow * 256);
            const uint32_t vlBs = sb + stgc + 2 * (H_VL + vrow * 256);
            const int vr7 = vrow & 7;
            #pragma unroll
            for (int G = 0; G < 8; G++) {
                unsigned vh4[4], vl4[4];
                uint32_t vc = (uint32_t)((((wk * 16 + 2 * G + acs)) ^ vr7) << 4);
                ldsm4t(vh4, vhBs + vc);
                ldsm4t(vl4, vlBs + vc);
                int gg = 2 * G;
                mma_f16(o[gg],     pa,  &vh4[0]);
                mma_f16(o[gg],     pl4, &vh4[0]);
                mma_f16(o[gg],     pa,  &vl4[0]);
                mma_f16(o[gg + 1], pa,  &vh4[2]);
                mma_f16(o[gg + 1], pl4, &vh4[2]);
                mma_f16(o[gg + 1], pa,  &vl4[2]);
            }
        }
    }

    __syncthreads();
    const float il0 = 1.0f / fpm[F_L + rA];
    const float il1 = 1.0f / fpm[F_L + rA + 8];
    #pragma unroll
    for (int g = 0; g < 16; g++) {
        int col = h * HD + wk * 128 + g * 8 + 2 * cL;
        *(__half2*)(outp + (size_t)(t0 + rA) * HIDDEN + col) =
            __floats2half2_rn(o[g][0] * il0, o[g][1] * il0);
        *(__half2*)(outp + (size_t)(t0 + rA + 8) * HIDDEN + col) =
            __floats2half2_rn(o[g][2] * il1, o[g][3] * il1);
    }
}

// ---------------------------------------------------------------------------
// launch
// ---------------------------------------------------------------------------
extern "C" void kernel_launch(void* const* d_in, const int* in_sizes, int n_in,
                              void* d_out, int out_size)
{
    const float* hidden = (const float*)d_in[0];
    const float* w_qkv  = (const float*)d_in[1];
    const float* w_o    = (const float*)d_in[2];
    const float* cosp   = (const float*)d_in[3];
    const float* sinp   = (const float*)d_in[4];
    // d_in[5..8] (caches, slots, batch_size) unused: cache write+gather is identity.

    float*  qkv;  cudaGetSymbolAddress((void**)&qkv,  g_qkv);
    __half* at16; cudaGetSymbolAddress((void**)&at16, g_attn16);
    __half* h16;  cudaGetSymbolAddress((void**)&h16,  g_hid16);
    __half* wq16; cudaGetSymbolAddress((void**)&wq16, g_wq16);
    __half* wo16; cudaGetSymbolAddress((void**)&wo16, g_wo16);
    __half *qh, *ql, *kh, *kl, *vh, *vl;
    cudaGetSymbolAddress((void**)&qh, g_qh);
    cudaGetSymbolAddress((void**)&ql, g_ql);
    cudaGetSymbolAddress((void**)&kh, g_kh);
    cudaGetSymbolAddress((void**)&kl, g_kl);
    cudaGetSymbolAddress((void**)&vh, g_vh);
    cudaGetSymbolAddress((void**)&vl, g_vl);

    cudaFuncSetAttribute(gemm_h, cudaFuncAttributeMaxDynamicSharedMemorySize, GEMM_SMEM);
    cudaFuncSetAttribute(attn_h, cudaFuncAttributeMaxDynamicSharedMemorySize, ATT_SMEM);

    // 0) fp16 conversion pre-pass (single launch, three segments)
    {
        size_t total = F2H_N0 + F2H_N1 + F2H_N2;
        f2h_all<<<(unsigned)((total + 255) / 256), 256>>>(
            hidden, h16, w_qkv, wq16, w_o, wo16);
    }
    // 1) qkv = hidden @ w_qkv^T
    {
        dim3 grid(QKV_W / GTILE_N, T_TOK / GTILE_M);   // (96, 64)
        gemm_h<<<grid, 128, GEMM_SMEM>>>(h16, wq16, qkv, T_TOK, QKV_W, HIDDEN);
    }
    // 2) RoPE + hi/lo split of q,k,v (single-touch)
    prep_kernel<<<(T_TOK * NHEAD * 64) / 256, 256>>>(qkv, cosp, sinp,
                                                     qh, ql, kh, kl, vh, vl);
    // 3) fp16 3-pass flash attention (double-buffered cp.async) -> fp16
    {
        dim3 grid(SEQ / AQ, BATCH * NHEAD);
        attn_h<<<grid, 256, ATT_SMEM>>>(qh, ql, kh, kl, vh, vl, at16);
    }
    // 4) out = attn @ w_o^T
    {
        dim3 grid(HIDDEN / GTILE_N, T_TOK / GTILE_M);  // (32, 64)
        gemm_h<<<grid, 128, GEMM_SMEM>>>(at16, wo16, (float*)d_out, T_TOK, HIDDEN, HIDDEN);
    }
}

// round 16
// speedup vs baseline: 1.0470x; 1.0123x over previous
#include <cuda_runtime.h>
#include <cuda_fp16.h>
#include <math.h>
#include <stdint.h>

// ---------------------------------------------------------------------------
// Problem constants
// ---------------------------------------------------------------------------
#define T_TOK   8192
#define HIDDEN  4096
#define NHEAD   16
#define HD      256
#define QKV_W   (3 * HIDDEN)     // 12288
#define BATCH   8
#define SEQ     1024
#define ROT_H   32               // rotary_dim/2

// Scratch (device globals: allocation-free rule)
__device__ float  g_qkv[(size_t)T_TOK * QKV_W];      // 8192 x 12288 fp32
__device__ __half g_attn16[(size_t)T_TOK * HIDDEN];  // attention out (fp16)
__device__ __half g_hid16[(size_t)T_TOK * HIDDEN];   // fp16 hidden
__device__ __half g_wq16 [(size_t)QKV_W * HIDDEN];   // fp16 w_qkv
__device__ __half g_wo16 [(size_t)HIDDEN * HIDDEN];  // fp16 w_o
// pre-split (RoPE-applied) q/k/v hi/lo halves, [T][16][256] each
__device__ __half g_qh[(size_t)T_TOK * HIDDEN];
__device__ __half g_ql[(size_t)T_TOK * HIDDEN];
__device__ __half g_kh[(size_t)T_TOK * HIDDEN];
__device__ __half g_kl[(size_t)T_TOK * HIDDEN];
__device__ __half g_vh[(size_t)T_TOK * HIDDEN];
__device__ __half g_vl[(size_t)T_TOK * HIDDEN];

// ---------------------------------------------------------------------------
// helpers
// ---------------------------------------------------------------------------
__device__ __forceinline__ uint32_t smem_u32(const void* p) {
    uint32_t a;
    asm("{ .reg .u64 t; cvta.to.shared.u64 t, %1; cvt.u32.u64 %0, t; }"
        : "=r"(a) : "l"(p));
    return a;
}

__device__ __forceinline__ void mma_f16(float* d, const unsigned* a, const unsigned* b) {
    asm volatile(
        "mma.sync.aligned.m16n8k16.row.col.f32.f16.f16.f32 "
        "{%0,%1,%2,%3}, {%4,%5,%6,%7}, {%8,%9}, {%0,%1,%2,%3};\n"
        : "+f"(d[0]), "+f"(d[1]), "+f"(d[2]), "+f"(d[3])
        : "r"(a[0]), "r"(a[1]), "r"(a[2]), "r"(a[3]),
          "r"(b[0]), "r"(b[1]));
}

__device__ __forceinline__ void ldsm4(unsigned* r, uint32_t addr) {
    asm volatile("ldmatrix.sync.aligned.m8n8.x4.shared.b16 {%0,%1,%2,%3}, [%4];"
        : "=r"(r[0]), "=r"(r[1]), "=r"(r[2]), "=r"(r[3]) : "r"(addr));
}
__device__ __forceinline__ void ldsm4t(unsigned* r, uint32_t addr) {
    asm volatile("ldmatrix.sync.aligned.m8n8.x4.trans.shared.b16 {%0,%1,%2,%3}, [%4];"
        : "=r"(r[0]), "=r"(r[1]), "=r"(r[2]), "=r"(r[3]) : "r"(addr));
}

__device__ __forceinline__ void cp16(uint32_t dst, const void* src) {
    asm volatile("cp.async.cg.shared.global [%0], [%1], 16;"
                 :: "r"(dst), "l"(src) : "memory");
}
#define CP_COMMIT()  asm volatile("cp.async.commit_group;" ::: "memory")
#define CP_WAITG2()  asm volatile("cp.async.wait_group 2;" ::: "memory")
#define CP_WAIT0()   asm volatile("cp.async.wait_group 0;" ::: "memory")

// split fp32x4 -> (hi fp16 x4, lo fp16 x4) and store 8B each
__device__ __forceinline__ void split_store(__half* bh, __half* bl, float4 v) {
    __half2 h0 = __floats2half2_rn(v.x, v.y);
    __half2 h1 = __floats2half2_rn(v.z, v.w);
    __half2 l0 = __floats2half2_rn(v.x - __low2float(h0), v.y - __high2float(h0));
    __half2 l1 = __floats2half2_rn(v.z - __low2float(h1), v.w - __high2float(h1));
    *(__half2*)(bh)     = h0;  *(__half2*)(bh + 2) = h1;
    *(__half2*)(bl)     = l0;  *(__half2*)(bl + 2) = l1;
}

// RoPE rotate a float4 at rotary chunk c4 (<16); base = &x[c4*4], partner +-32
__device__ __forceinline__ float4 rope_rot(
    const float* base, int c4, int t,
    const float* __restrict__ cosp, const float* __restrict__ sinp, float4 v)
{
    if (c4 < 8) {
        float4 x2 = *(const float4*)(base + 32);
        float4 cc = *(const float4*)(cosp + (size_t)t * ROT_H + c4 * 4);
        float4 ss = *(const float4*)(sinp + (size_t)t * ROT_H + c4 * 4);
        v.x = v.x * cc.x - x2.x * ss.x;
        v.y = v.y * cc.y - x2.y * ss.y;
        v.z = v.z * cc.z - x2.z * ss.z;
        v.w = v.w * cc.w - x2.w * ss.w;
    } else {
        float4 x1 = *(const float4*)(base - 32);
        int d4 = (c4 - 8) * 4;
        float4 cc = *(const float4*)(cosp + (size_t)t * ROT_H + d4);
        float4 ss = *(const float4*)(sinp + (size_t)t * ROT_H + d4);
        v.x = v.x * cc.x + x1.x * ss.x;
        v.y = v.y * cc.y + x1.y * ss.y;
        v.z = v.z * cc.z + x1.z * ss.z;
        v.w = v.w * cc.w + x1.w * ss.w;
    }
    return v;
}

// ---------------------------------------------------------------------------
// fp32 -> fp16 conversion pre-pass (rn): one launch covers hidden,w_qkv,w_o
// ---------------------------------------------------------------------------
#define F2H_N0 ((size_t)T_TOK * HIDDEN / 4)
#define F2H_N1 ((size_t)QKV_W * HIDDEN / 4)
#define F2H_N2 ((size_t)HIDDEN * HIDDEN / 4)

__global__ __launch_bounds__(256) void f2h_all(
    const float* __restrict__ s0, __half* __restrict__ d0,
    const float* __restrict__ s1, __half* __restrict__ d1,
    const float* __restrict__ s2, __half* __restrict__ d2)
{
    size_t i = (size_t)blockIdx.x * 256 + threadIdx.x;
    const float* src; __half* dst;
    if (i < F2H_N0) { src = s0; dst = d0; }
    else if (i < F2H_N0 + F2H_N1) { i -= F2H_N0; src = s1; dst = d1; }
    else { i -= F2H_N0 + F2H_N1; src = s2; dst = d2; }
    float4 v = *(const float4*)(src + i * 4);
    *(__half2*)(dst + i * 4)     = __floats2half2_rn(v.x, v.y);
    *(__half2*)(dst + i * 4 + 2) = __floats2half2_rn(v.z, v.w);
}

// ---------------------------------------------------------------------------
// prep: RoPE (q,k) + hi/lo split of q,k,v into persistent fp16 arrays.
// ---------------------------------------------------------------------------
__global__ __launch_bounds__(256) void prep_kernel(
    const float* __restrict__ qkv,
    const float* __restrict__ cosp, const float* __restrict__ sinp,
    __half* __restrict__ qh, __half* __restrict__ ql,
    __half* __restrict__ kh, __half* __restrict__ kl,
    __half* __restrict__ vh, __half* __restrict__ vl)
{
    int idx = blockIdx.x * 256 + threadIdx.x;   // over T*16*64
    int c4 = idx & 63;
    int h  = (idx >> 6) & 15;
    int t  = idx >> 10;
    const float* qb = qkv + (size_t)t * QKV_W + h * HD + c4 * 4;
    float4 qv = *(const float4*)qb;
    float4 kv = *(const float4*)(qb + HIDDEN);
    float4 vv = *(const float4*)(qb + 2 * HIDDEN);
    if (c4 < 16) {
        qv = rope_rot(qb, c4, t, cosp, sinp, qv);
        kv = rope_rot(qb + HIDDEN, c4, t, cosp, sinp, kv);
    }
    size_t o = (size_t)t * HIDDEN + h * HD + c4 * 4;
    split_store(qh + o, ql + o, qv);
    split_store(kh + o, kl + o, kv);
    split_store(vh + o, vl + o, vv);
}

// ---------------------------------------------------------------------------
// fp16 mma.sync GEMM (NT) — R7 byte-identical (empirically optimal config).
// ---------------------------------------------------------------------------
#define GTILE_M   128
#define GTILE_N   128
#define KTILE     32
#define ROW_B     80
#define A_ST_B    (128 * ROW_B)            // 10240 B
#define STAGE_B   (2 * A_ST_B)             // 20480 B
#define NSTG      4
#define GEMM_SMEM (NSTG * STAGE_B)         // 81920 B

__global__ __launch_bounds__(128, 2) void gemm_h(
    const __half* __restrict__ A, const __half* __restrict__ B,
    float* __restrict__ C, int M, int N, int K)
{
    extern __shared__ __align__(128) char smc[];
    const uint32_t sb = smem_u32(smc);

    const int tid  = threadIdx.x;
    const int lane = tid & 31;
    const int wid  = tid >> 5;
    const int wm   = wid >> 1;
    const int wn   = wid & 1;

    const int Nb = gridDim.x;
    const int Mb = gridDim.y;
    int linear = blockIdx.y * Nb + blockIdx.x;
    int group  = linear / (Nb * 8);
    int rem    = linear - group * (Nb * 8);
    int mstart = group * 8;
    int mspan  = Mb - mstart; if (mspan > 8) mspan = 8;
    int mb_id  = mstart + rem % mspan;
    int nb_id  = rem / mspan;
    const int m0 = mb_id * GTILE_M;
    const int n0 = nb_id * GTILE_N;

    const __half* srcA[4];  uint32_t dstA[4];
    const __half* srcB[4];  uint32_t dstB[4];
    #pragma unroll
    for (int i = 0; i < 4; i++) {
        int idx = tid + 128 * i;
        int row = idx >> 2, c = idx & 3;
        srcA[i] = A + (size_t)(m0 + row) * K + c * 8;
        dstA[i] = (uint32_t)(row * ROW_B + c * 16);
        srcB[i] = B + (size_t)(n0 + row) * K + c * 8;
        dstB[i] = (uint32_t)(A_ST_B + row * ROW_B + c * 16);
    }

    const int NT = K >> 5;

    #pragma unroll
    for (int s = 0; s < 3; s++) {
        const uint32_t st = sb + s * STAGE_B;
        #pragma unroll
        for (int i = 0; i < 4; i++) cp16(st + dstA[i], srcA[i] + s * KTILE);
        #pragma unroll
        for (int i = 0; i < 4; i++) cp16(st + dstB[i], srcB[i] + s * KTILE);
        CP_COMMIT();
    }

    float acc[4][8][4];
    #pragma unroll
    for (int f = 0; f < 4; f++)
        #pragma unroll
        for (int g = 0; g < 8; g++)
            #pragma unroll
            for (int r = 0; r < 4; r++) acc[f][g][r] = 0.f;

    const uint32_t aLane = (uint32_t)((wm * 64 + (lane & 15)) * ROW_B + ((lane >> 4) << 4));
    const uint32_t bLane = (uint32_t)(A_ST_B +
        (wn * 64 + ((lane >> 4) << 3) + (lane & 7)) * ROW_B + (((lane >> 3) & 1) << 4));

    for (int kt = 0; kt < NT; kt++) {
        CP_WAITG2();
        __syncthreads();

        if (kt + 3 < NT) {
            const uint32_t st = sb + ((kt + 3) % NSTG) * STAGE_B;
            const int ko = (kt + 3) * KTILE;
            #pragma unroll
            for (int i = 0; i < 4; i++) cp16(st + dstA[i], srcA[i] + ko);
            #pragma unroll
            for (int i = 0; i < 4; i++) cp16(st + dstB[i], srcB[i] + ko);
        }
        CP_COMMIT();

        const uint32_t stb = sb + (kt % NSTG) * STAGE_B;
        #pragma unroll
        for (int s = 0; s < 2; s++) {
            unsigned af[4][4], bf[4][4];
            #pragma unroll
            for (int f = 0; f < 4; f++)
                ldsm4(af[f], stb + aLane + f * (16 * ROW_B) + s * 32);
            #pragma unroll
            for (int g2 = 0; g2 < 4; g2++)
                ldsm4(bf[g2], stb + bLane + g2 * (16 * ROW_B) + s * 32);
            #pragma unroll
            for (int f = 0; f < 4; f++)
                #pragma unroll
                for (int g = 0; g < 8; g++)
                    mma_f16(acc[f][g], af[f], &bf[g >> 1][(g & 1) * 2]);
        }
    }

    const int r = lane >> 2;
    const int c = lane & 3;
    #pragma unroll
    for (int f = 0; f < 4; f++) {
        int row = m0 + wm * 64 + f * 16 + r;
        #pragma unroll
        for (int g = 0; g < 8; g++) {
            int col = n0 + wn * 64 + g * 8 + c * 2;
            float* cp = C + (size_t)row * N + col;
            *(float2*)cp = make_float2(acc[f][g][0], acc[f][g][1]);
            *(float2*)(cp + (size_t)8 * N) = make_float2(acc[f][g][2], acc[f][g][3]);
        }
    }
}

// ---------------------------------------------------------------------------
// fp16 3-pass compensated flash attention (causal), double-buffered k/v.
// NEW: static-shift softmax p = exp(s - 4) — no online max, no alpha rescale,
// no cross-warp max exchange; l accumulated in registers, reduced once at end.
// exp(s-4) cancels in the final 1/l normalization (exact softmax).
// ---------------------------------------------------------------------------
#define AQ 64
#define AKT 32
// smem half-offsets
#define H_QH 0
#define H_QL 16384
#define H_KH 32768               // stage 0; stage 1 = +KV_STG_H
#define H_KL 40960
#define H_VH 49152
#define H_VL 57344
#define KV_STG_H 32768
#define KV_STG_B 65536
#define H_PH 98304
#define H_PL 102400
// stats in FLOAT units (half index 106496 -> float 53248)
#define F_PS 53248               // 128 floats: [wk][row]
#define ATT_SMEM  214528

__global__ __launch_bounds__(256, 1) void attn_h(
    const __half* __restrict__ qhg, const __half* __restrict__ qlg,
    const __half* __restrict__ khg, const __half* __restrict__ klg,
    const __half* __restrict__ vhg, const __half* __restrict__ vlg,
    __half* __restrict__ outp)
{
    extern __shared__ char sm[];
    __half* hp = (__half*)sm;
    float*  fpm = (float*)sm;
    const uint32_t sb = smem_u32(sm);

    const int tid = threadIdx.x, lane = tid & 31, w = tid >> 5;
    const int qt = 15 - blockIdx.x;
    const int bh = blockIdx.y;
    const int b = bh >> 4, h = bh & 15;
    const int t0 = b * SEQ + qt * AQ;
    const int wq = w & 3, wk = w >> 2;
    const int cL = lane & 3;
    const int rL = lane >> 2;
    const int rA = wq * 16 + rL;
    const int hoff = h * HD;
    const int ktmax = 2 * qt + 1;

    // ---- q tile via cp.async ----
    #pragma unroll
    for (int i = 0; i < 16; i++) {
        const __half* srcb = (i < 8) ? qhg : qlg;
        const uint32_t hbase = (i < 8) ? H_QH : H_QL;
        int rem = tid + 256 * (i & 7);
        int row = rem >> 5, ch = rem & 31;
        cp16(sb + 2 * (hbase + row * 256 + ((ch ^ (row & 7)) << 3)),
             srcb + (size_t)(t0 + row) * HIDDEN + hoff + ch * 8);
    }
    CP_COMMIT();
    // ---- k/v tile 0 into stage 0 ----
    {
        const int tk = b * SEQ;
        #pragma unroll
        for (int i = 0; i < 16; i++) {
            const __half* srcb = (i < 4) ? khg : (i < 8) ? klg : (i < 12) ? vhg : vlg;
            const uint32_t hbase = (i < 4) ? H_KH : (i < 8) ? H_KL : (i < 12) ? H_VH : H_VL;
            int rem = tid + 256 * (i & 3);
            int row = rem >> 5, ch = rem & 31;
            cp16(sb + 2 * (hbase + row * 256 + ((ch ^ (row & 7)) << 3)),
                 srcb + (size_t)(tk + row) * HIDDEN + hoff + ch * 8);
        }
        CP_COMMIT();
    }

    float o[16][4];
    #pragma unroll
    for (int g = 0; g < 16; g++)
        #pragma unroll
        for (int r = 0; r < 4; r++) o[g][r] = 0.f;
    float lsum0 = 0.f, lsum1 = 0.f;   // per-thread partial softmax sums

    const int arow  = wq * 16 + (lane & 15);
    const int krow  = wk * 16 + ((lane & 7) | ((lane >> 4) << 3));
    const int vk    = lane & 15;
    const int acs   = lane >> 4;
    const int bcs   = (lane >> 3) & 1;
    const uint32_t qhB = sb + 2 * (H_QH + arow * 256);
    const uint32_t qlB = sb + 2 * (H_QL + arow * 256);
    const uint32_t khB = sb + 2 * (H_KH + krow * 256);
    const uint32_t klB = sb + 2 * (H_KL + krow * 256);
    const uint32_t phB = sb + 2 * (H_PH + arow * 64);
    const uint32_t plB = sb + 2 * (H_PL + arow * 64);
    const int arow7 = arow & 7, krow7 = krow & 7;

    for (int kt = 0; kt <= ktmax; kt++) {
        CP_WAIT0();        // tile kt resident (q too, at kt=0)
        __syncthreads();   // all warps done with the other stage + prev p reads

        // prefetch tile kt+1 into the other stage (overlaps compute below)
        if (kt < ktmax) {
            const int tk = b * SEQ + (kt + 1) * AKT;
            const uint32_t stg = ((kt + 1) & 1) ? (uint32_t)KV_STG_B : 0u;
            #pragma unroll
            for (int i = 0; i < 16; i++) {
                const __half* srcb = (i < 4) ? khg : (i < 8) ? klg : (i < 12) ? vhg : vlg;
                const uint32_t hbase = (i < 4) ? H_KH : (i < 8) ? H_KL : (i < 12) ? H_VH : H_VL;
                int rem = tid + 256 * (i & 3);
                int row = rem >> 5, ch = rem & 31;
                cp16(stg + sb + 2 * (hbase + row * 256 + ((ch ^ (row & 7)) << 3)),
                     srcb + (size_t)(tk + row) * HIDDEN + hoff + ch * 8);
            }
            CP_COMMIT();
        }

        const uint32_t stgc = (kt & 1) ? (uint32_t)KV_STG_B : 0u;

        float sacc[2][4];
        #pragma unroll
        for (int g = 0; g < 2; g++)
            #pragma unroll
            for (int r = 0; r < 4; r++) sacc[g][r] = 0.f;

        #pragma unroll
        for (int s = 0; s < 16; s++) {
            unsigned ah[4], al2[4], bh2[4], bl2[4];
            uint32_t ac = (uint32_t)(((2 * s + acs) ^ arow7) << 4);
            uint32_t bc = (uint32_t)(((2 * s + bcs) ^ krow7) << 4);
            ldsm4(ah, qhB + ac);
            ldsm4(al2, qlB + ac);
            ldsm4(bh2, khB + stgc + bc);
            ldsm4(bl2, klB + stgc + bc);
            #pragma unroll
            for (int g = 0; g < 2; g++) {
                mma_f16(sacc[g], ah,  &bh2[2 * g]);
                mma_f16(sacc[g], al2, &bh2[2 * g]);
                mma_f16(sacc[g], ah,  &bl2[2 * g]);
            }
        }

        if (kt >= 2 * qt) {   // causal mask on diagonal tiles
            #pragma unroll
            for (int g = 0; g < 2; g++)
                #pragma unroll
                for (int r = 0; r < 4; r++) {
                    int col = kt * AKT + wk * 16 + g * 8 + 2 * cL + (r & 1);
                    int row = qt * AQ + rA + 8 * (r >> 1);
                    if (col > row) sacc[g][r] = -1e30f;
                }
        }

        // ---- p = exp(s/16 - 4); accumulate l; split-store to smem ----
        #pragma unroll
        for (int g = 0; g < 2; g++) {
            float p0 = __expf(sacc[g][0] * 0.0625f - 4.0f);
            float p1 = __expf(sacc[g][1] * 0.0625f - 4.0f);
            float p2 = __expf(sacc[g][2] * 0.0625f - 4.0f);
            float p3 = __expf(sacc[g][3] * 0.0625f - 4.0f);
            lsum0 += p0 + p1; lsum1 += p2 + p3;
            __half2 h01 = __floats2half2_rn(p0, p1);
            __half2 h23 = __floats2half2_rn(p2, p3);
            __half2 l01 = __floats2half2_rn(p0 - __low2float(h01), p1 - __high2float(h01));
            __half2 l23 = __floats2half2_rn(p2 - __low2float(h23), p3 - __high2float(h23));
            int pc = wk * 2 + g;
            uint32_t o0 = H_PH + rA * 64 + ((pc ^ (rA & 7)) << 3) + 2 * cL;
            uint32_t o1 = H_PH + (rA + 8) * 64 + ((pc ^ (rA & 7)) << 3) + 2 * cL;
            *(__half2*)&hp[o0] = h01;
            *(__half2*)&hp[o1] = h23;
            *(__half2*)&hp[o0 + (H_PL - H_PH)] = l01;
            *(__half2*)&hp[o1 + (H_PL - H_PH)] = l23;
        }
        __syncthreads();   // p visible to all warps

        // ---- PV: s selects k16 half; v rows = s*16 + (lane&15) ----
        #pragma unroll
        for (int s = 0; s < 2; s++) {
            unsigned pa[4], pl4[4];
            uint32_t pc = (uint32_t)(((2 * s + acs) ^ arow7) << 4);
            ldsm4(pa, phB + pc);
            ldsm4(pl4, plB + pc);
            const uint32_t vrow = s * 16 + vk;
            const uint32_t vhBs = sb + stgc + 2 * (H_VH + vrow * 256);
            const uint32_t vlBs = sb + stgc + 2 * (H_VL + vrow * 256);
            const int vr7 = vrow & 7;
            #pragma unroll
            for (int G = 0; G < 8; G++) {
                unsigned vh4[4], vl4[4];
                uint32_t vc = (uint32_t)((((wk * 16 + 2 * G + acs)) ^ vr7) << 4);
                ldsm4t(vh4, vhBs + vc);
                ldsm4t(vl4, vlBs + vc);
                int gg = 2 * G;
                mma_f16(o[gg],     pa,  &vh4[0]);
                mma_f16(o[gg],     pl4, &vh4[0]);
                mma_f16(o[gg],     pa,  &vl4[0]);
                mma_f16(o[gg + 1], pa,  &vh4[2]);
                mma_f16(o[gg + 1], pl4, &vh4[2]);
                mma_f16(o[gg + 1], pa,  &vl4[2]);
            }
        }
    }

    // ---- final l reduction: over cL lanes, then across wk warps ----
    lsum0 += __shfl_xor_sync(0xffffffffu, lsum0, 1);
    lsum0 += __shfl_xor_sync(0xffffffffu, lsum0, 2);
    lsum1 += __shfl_xor_sync(0xffffffffu, lsum1, 1);
    lsum1 += __shfl_xor_sync(0xffffffffu, lsum1, 2);
    __syncthreads();
    if (cL == 0) {
        fpm[F_PS + wk * 64 + rA]     = lsum0;
        fpm[F_PS + wk * 64 + rA + 8] = lsum1;
    }
    __syncthreads();
    const float il0 = 1.0f / (fpm[F_PS + rA]     + fpm[F_PS + 64 + rA]);
    const float il1 = 1.0f / (fpm[F_PS + rA + 8] + fpm[F_PS + 64 + rA + 8]);
    #pragma unroll
    for (int g = 0; g < 16; g++) {
        int col = h * HD + wk * 128 + g * 8 + 2 * cL;
        *(__half2*)(outp + (size_t)(t0 + rA) * HIDDEN + col) =
            __floats2half2_rn(o[g][0] * il0, o[g][1] * il0);
        *(__half2*)(outp + (size_t)(t0 + rA + 8) * HIDDEN + col) =
            __floats2half2_rn(o[g][2] * il1, o[g][3] * il1);
    }
}

// ---------------------------------------------------------------------------
// launch
// ---------------------------------------------------------------------------
extern "C" void kernel_launch(void* const* d_in, const int* in_sizes, int n_in,
                              void* d_out, int out_size)
{
    const float* hidden = (const float*)d_in[0];
    const float* w_qkv  = (const float*)d_in[1];
    const float* w_o    = (const float*)d_in[2];
    const float* cosp   = (const float*)d_in[3];
    const float* sinp   = (const float*)d_in[4];
    // d_in[5..8] (caches, slots, batch_size) unused: cache write+gather is identity.

    float*  qkv;  cudaGetSymbolAddress((void**)&qkv,  g_qkv);
    __half* at16; cudaGetSymbolAddress((void**)&at16, g_attn16);
    __half* h16;  cudaGetSymbolAddress((void**)&h16,  g_hid16);
    __half* wq16; cudaGetSymbolAddress((void**)&wq16, g_wq16);
    __half* wo16; cudaGetSymbolAddress((void**)&wo16, g_wo16);
    __half *qh, *ql, *kh, *kl, *vh, *vl;
    cudaGetSymbolAddress((void**)&qh, g_qh);
    cudaGetSymbolAddress((void**)&ql, g_ql);
    cudaGetSymbolAddress((void**)&kh, g_kh);
    cudaGetSymbolAddress((void**)&kl, g_kl);
    cudaGetSymbolAddress((void**)&vh, g_vh);
    cudaGetSymbolAddress((void**)&vl, g_vl);

    cudaFuncSetAttribute(gemm_h, cudaFuncAttributeMaxDynamicSharedMemorySize, GEMM_SMEM);
    cudaFuncSetAttribute(attn_h, cudaFuncAttributeMaxDynamicSharedMemorySize, ATT_SMEM);

    // 0) fp16 conversion pre-pass (single launch, three segments)
    {
        size_t total = F2H_N0 + F2H_N1 + F2H_N2;
        f2h_all<<<(unsigned)((total + 255) / 256), 256>>>(
            hidden, h16, w_qkv, wq16, w_o, wo16);
    }
    // 1) qkv = hidden @ w_qkv^T
    {
        dim3 grid(QKV_W / GTILE_N, T_TOK / GTILE_M);   // (96, 64)
        gemm_h<<<grid, 128, GEMM_SMEM>>>(h16, wq16, qkv, T_TOK, QKV_W, HIDDEN);
    }
    // 2) RoPE + hi/lo split of q,k,v (single-touch)
    prep_kernel<<<(T_TOK * NHEAD * 64) / 256, 256>>>(qkv, cosp, sinp,
                                                     qh, ql, kh, kl, vh, vl);
    // 3) fp16 static-shift-softmax flash attention (double-buffered) -> fp16
    {
        dim3 grid(SEQ / AQ, BATCH * NHEAD);
        attn_h<<<grid, 256, ATT_SMEM>>>(qh, ql, kh, kl, vh, vl, at16);
    }
    // 4) out = attn @ w_o^T
    {
        dim3 grid(HIDDEN / GTILE_N, T_TOK / GTILE_M);  // (32, 64)
        gemm_h<<<grid, 128, GEMM_SMEM>>>(at16, wo16, (float*)d_out, T_TOK, HIDDEN, HIDDEN);
    }
}

// round 17
// speedup vs baseline: 1.0644x; 1.0167x over previous
#include <cuda_runtime.h>
#include <cuda_fp16.h>
#include <math.h>
#include <stdint.h>

// ---------------------------------------------------------------------------
// Problem constants
// ---------------------------------------------------------------------------
#define T_TOK   8192
#define HIDDEN  4096
#define NHEAD   16
#define HD      256
#define QKV_W   (3 * HIDDEN)     // 12288
#define BATCH   8
#define SEQ     1024
#define ROT_H   32               // rotary_dim/2

// Scratch (device globals: allocation-free rule)
__device__ __half g_attn16[(size_t)T_TOK * HIDDEN];  // attention out (fp16)
__device__ __half g_hid16[(size_t)T_TOK * HIDDEN];   // fp16 hidden
__device__ __half g_wq16 [(size_t)QKV_W * HIDDEN];   // fp16 w_qkv
__device__ __half g_wo16 [(size_t)HIDDEN * HIDDEN];  // fp16 w_o
// pre-split (RoPE-applied) q/k/v hi/lo halves, [T][16][256] each
__device__ __half g_qh[(size_t)T_TOK * HIDDEN];
__device__ __half g_ql[(size_t)T_TOK * HIDDEN];
__device__ __half g_kh[(size_t)T_TOK * HIDDEN];
__device__ __half g_kl[(size_t)T_TOK * HIDDEN];
__device__ __half g_vh[(size_t)T_TOK * HIDDEN];
__device__ __half g_vl[(size_t)T_TOK * HIDDEN];

// ---------------------------------------------------------------------------
// helpers
// ---------------------------------------------------------------------------
__device__ __forceinline__ uint32_t smem_u32(const void* p) {
    uint32_t a;
    asm("{ .reg .u64 t; cvta.to.shared.u64 t, %1; cvt.u32.u64 %0, t; }"
        : "=r"(a) : "l"(p));
    return a;
}

__device__ __forceinline__ void mma_f16(float* d, const unsigned* a, const unsigned* b) {
    asm volatile(
        "mma.sync.aligned.m16n8k16.row.col.f32.f16.f16.f32 "
        "{%0,%1,%2,%3}, {%4,%5,%6,%7}, {%8,%9}, {%0,%1,%2,%3};\n"
        : "+f"(d[0]), "+f"(d[1]), "+f"(d[2]), "+f"(d[3])
        : "r"(a[0]), "r"(a[1]), "r"(a[2]), "r"(a[3]),
          "r"(b[0]), "r"(b[1]));
}

__device__ __forceinline__ void ldsm4(unsigned* r, uint32_t addr) {
    asm volatile("ldmatrix.sync.aligned.m8n8.x4.shared.b16 {%0,%1,%2,%3}, [%4];"
        : "=r"(r[0]), "=r"(r[1]), "=r"(r[2]), "=r"(r[3]) : "r"(addr));
}
__device__ __forceinline__ void ldsm4t(unsigned* r, uint32_t addr) {
    asm volatile("ldmatrix.sync.aligned.m8n8.x4.trans.shared.b16 {%0,%1,%2,%3}, [%4];"
        : "=r"(r[0]), "=r"(r[1]), "=r"(r[2]), "=r"(r[3]) : "r"(addr));
}

__device__ __forceinline__ void cp16(uint32_t dst, const void* src) {
    asm volatile("cp.async.cg.shared.global [%0], [%1], 16;"
                 :: "r"(dst), "l"(src) : "memory");
}
#define CP_COMMIT()  asm volatile("cp.async.commit_group;" ::: "memory")
#define CP_WAITG2()  asm volatile("cp.async.wait_group 2;" ::: "memory")
#define CP_WAIT0()   asm volatile("cp.async.wait_group 0;" ::: "memory")

// split 2 fp32 -> hi/lo fp16 pairs, store 4B each
__device__ __forceinline__ void split2_store(__half* dh, __half* dl, float a, float b) {
    __half2 hh = __floats2half2_rn(a, b);
    __half2 ll = __floats2half2_rn(a - __low2float(hh), b - __high2float(hh));
    *(__half2*)dh = hh;
    *(__half2*)dl = ll;
}

// ---------------------------------------------------------------------------
// fp32 -> fp16 conversion pre-pass (rn): one launch covers hidden,w_qkv,w_o
// ---------------------------------------------------------------------------
#define F2H_N0 ((size_t)T_TOK * HIDDEN / 4)
#define F2H_N1 ((size_t)QKV_W * HIDDEN / 4)
#define F2H_N2 ((size_t)HIDDEN * HIDDEN / 4)

__global__ __launch_bounds__(256) void f2h_all(
    const float* __restrict__ s0, __half* __restrict__ d0,
    const float* __restrict__ s1, __half* __restrict__ d1,
    const float* __restrict__ s2, __half* __restrict__ d2)
{
    size_t i = (size_t)blockIdx.x * 256 + threadIdx.x;
    const float* src; __half* dst;
    if (i < F2H_N0) { src = s0; dst = d0; }
    else if (i < F2H_N0 + F2H_N1) { i -= F2H_N0; src = s1; dst = d1; }
    else { i -= F2H_N0 + F2H_N1; src = s2; dst = d2; }
    float4 v = *(const float4*)(src + i * 4);
    *(__half2*)(dst + i * 4)     = __floats2half2_rn(v.x, v.y);
    *(__half2*)(dst + i * 4 + 2) = __floats2half2_rn(v.z, v.w);
}

// ---------------------------------------------------------------------------
// Shared GEMM mainloop config — R7 byte-identical (empirically optimal).
// CTA 128x128, 128 threads (2x2 warps of 64x64), KTILE 32, NSTG 4,
// wait_group 2, one __syncthreads per k-tile, 2 CTAs/SM, rows padded to 80B.
// ---------------------------------------------------------------------------
#define GTILE_M   128
#define GTILE_N   128
#define KTILE     32
#define ROW_B     80
#define A_ST_B    (128 * ROW_B)            // 10240 B
#define STAGE_B   (2 * A_ST_B)             // 20480 B
#define NSTG      4
#define GEMM_SMEM (NSTG * STAGE_B)         // 81920 B

// Mainloop body as a macro so both GEMM variants share identical code.
#define GEMM_MAINLOOP(A_, B_, K_)                                              \
    const __half* srcA[4];  uint32_t dstA[4];                                  \
    const __half* srcB[4];  uint32_t dstB[4];                                  \
    _Pragma("unroll")                                                          \
    for (int i = 0; i < 4; i++) {                                              \
        int idx = tid + 128 * i;                                               \
        int row = idx >> 2, c = idx & 3;                                       \
        srcA[i] = A_ + (size_t)(m0 + row) * K_ + c * 8;                        \
        dstA[i] = (uint32_t)(row * ROW_B + c * 16);                            \
        srcB[i] = B_ + (size_t)(n0 + row) * K_ + c * 8;                        \
        dstB[i] = (uint32_t)(A_ST_B + row * ROW_B + c * 16);                   \
    }                                                                          \
    const int NT = K_ >> 5;                                                    \
    _Pragma("unroll")                                                          \
    for (int s = 0; s < 3; s++) {                                              \
        const uint32_t st = sb + s * STAGE_B;                                  \
        _Pragma("unroll")                                                      \
        for (int i = 0; i < 4; i++) cp16(st + dstA[i], srcA[i] + s * KTILE);   \
        _Pragma("unroll")                                                      \
        for (int i = 0; i < 4; i++) cp16(st + dstB[i], srcB[i] + s * KTILE);   \
        CP_COMMIT();                                                           \
    }                                                                          \
    float acc[4][8][4];                                                        \
    _Pragma("unroll")                                                          \
    for (int f = 0; f < 4; f++)                                                \
        _Pragma("unroll")                                                      \
        for (int g = 0; g < 8; g++)                                            \
            _Pragma("unroll")                                                  \
            for (int r = 0; r < 4; r++) acc[f][g][r] = 0.f;                    \
    const uint32_t aLane = (uint32_t)((wm * 64 + (lane & 15)) * ROW_B +        \
                                      ((lane >> 4) << 4));                     \
    const uint32_t bLane = (uint32_t)(A_ST_B +                                 \
        (wn * 64 + ((lane >> 4) << 3) + (lane & 7)) * ROW_B +                  \
        (((lane >> 3) & 1) << 4));                                             \
    for (int kt = 0; kt < NT; kt++) {                                          \
        CP_WAITG2();                                                           \
        __syncthreads();                                                       \
        if (kt + 3 < NT) {                                                     \
            const uint32_t st = sb + ((kt + 3) % NSTG) * STAGE_B;              \
            const int ko = (kt + 3) * KTILE;                                   \
            _Pragma("unroll")                                                  \
            for (int i = 0; i < 4; i++) cp16(st + dstA[i], srcA[i] + ko);      \
            _Pragma("unroll")                                                  \
            for (int i = 0; i < 4; i++) cp16(st + dstB[i], srcB[i] + ko);      \
        }                                                                      \
        CP_COMMIT();                                                           \
        const uint32_t stb = sb + (kt % NSTG) * STAGE_B;                       \
        _Pragma("unroll")                                                      \
        for (int s = 0; s < 2; s++) {                                          \
            unsigned af[4][4], bf[4][4];                                       \
            _Pragma("unroll")                                                  \
            for (int f = 0; f < 4; f++)                                        \
                ldsm4(af[f], stb + aLane + f * (16 * ROW_B) + s * 32);         \
            _Pragma("unroll")                                                  \
            for (int g2 = 0; g2 < 4; g2++)                                     \
                ldsm4(bf[g2], stb + bLane + g2 * (16 * ROW_B) + s * 32);       \
            _Pragma("unroll")                                                  \
            for (int f = 0; f < 4; f++)                                        \
                _Pragma("unroll")                                              \
                for (int g = 0; g < 8; g++)                                    \
                    mma_f16(acc[f][g], af[f], &bf[g >> 1][(g & 1) * 2]);       \
        }                                                                      \
    }

#define GEMM_PREAMBLE()                                                        \
    extern __shared__ __align__(128) char smc[];                               \
    const uint32_t sb = smem_u32(smc);                                         \
    const int tid  = threadIdx.x;                                              \
    const int lane = tid & 31;                                                 \
    const int wid  = tid >> 5;                                                 \
    const int wm   = wid >> 1;                                                 \
    const int wn   = wid & 1;                                                  \
    const int Nb = gridDim.x;                                                  \
    const int Mb = gridDim.y;                                                  \
    int linear = blockIdx.y * Nb + blockIdx.x;                                 \
    int group  = linear / (Nb * 8);                                            \
    int rem    = linear - group * (Nb * 8);                                    \
    int mstart = group * 8;                                                    \
    int mspan  = Mb - mstart; if (mspan > 8) mspan = 8;                        \
    int mb_id  = mstart + rem % mspan;                                         \
    int nb_id  = rem / mspan;                                                  \
    const int m0 = mb_id * GTILE_M;                                            \
    const int n0 = nb_id * GTILE_N;

// ---------------------------------------------------------------------------
// gemm_h: fp16 GEMM with fp32 C output (used for the O-projection)
// ---------------------------------------------------------------------------
__global__ __launch_bounds__(128, 2) void gemm_h(
    const __half* __restrict__ A, const __half* __restrict__ B,
    float* __restrict__ C, int M, int N, int K)
{
    GEMM_PREAMBLE();
    GEMM_MAINLOOP(A, B, K);

    const int r = lane >> 2;
    const int c = lane & 3;
    #pragma unroll
    for (int f = 0; f < 4; f++) {
        int row = m0 + wm * 64 + f * 16 + r;
        #pragma unroll
        for (int g = 0; g < 8; g++) {
            int col = n0 + wn * 64 + g * 8 + c * 2;
            float* cp = C + (size_t)row * N + col;
            *(float2*)cp = make_float2(acc[f][g][0], acc[f][g][1]);
            *(float2*)(cp + (size_t)8 * N) = make_float2(acc[f][g][2], acc[f][g][3]);
        }
    }
}

// ---------------------------------------------------------------------------
// gemm_qkv: SAME mainloop; epilogue applies RoPE (q,k rotary cols, fp32) and
// splits fp32 -> fp16 hi/lo directly into qh/ql/kh/kl/vh/vl. Eliminates the
// fp32 qkv array and the prep kernel round trip. Math chain identical:
// GEMM fp32 -> rope fp32 -> rn split.
// ---------------------------------------------------------------------------
__global__ __launch_bounds__(128, 2) void gemm_qkv(
    const __half* __restrict__ A, const __half* __restrict__ B,
    const float* __restrict__ cosp, const float* __restrict__ sinp,
    __half* __restrict__ qh, __half* __restrict__ ql,
    __half* __restrict__ kh, __half* __restrict__ kl,
    __half* __restrict__ vh, __half* __restrict__ vl)
{
    GEMM_PREAMBLE();
    GEMM_MAINLOOP(A, B, HIDDEN);

    const int r = lane >> 2;
    const int c = lane & 3;
    const int nbase = n0 + wn * 64;

    // region select (uniform per warp tile: boundaries are 4096-aligned)
    __half *dh, *dl;
    int cbase;
    if (nbase < HIDDEN)          { dh = qh; dl = ql; cbase = nbase; }
    else if (nbase < 2 * HIDDEN) { dh = kh; dl = kl; cbase = nbase - HIDDEN; }
    else                         { dh = vh; dl = vl; cbase = nbase - 2 * HIDDEN; }

    // fused RoPE: rotary cols (head-local 0..63) live in tiles with
    // nbase%256==0; pair (d, d+32) = acc tiles (g, g+4) of the same thread.
    if (((nbase & 255) == 0) && (nbase < 2 * HIDDEN)) {
        #pragma unroll
        for (int f = 0; f < 4; f++) {
            int row0 = m0 + wm * 64 + f * 16 + r;
            #pragma unroll
            for (int g = 0; g < 4; g++) {
                int d0 = g * 8 + c * 2;
                float2 c0 = *(const float2*)(cosp + (size_t)row0 * ROT_H + d0);
                float2 s0 = *(const float2*)(sinp + (size_t)row0 * ROT_H + d0);
                float2 c1 = *(const float2*)(cosp + (size_t)(row0 + 8) * ROT_H + d0);
                float2 s1 = *(const float2*)(sinp + (size_t)(row0 + 8) * ROT_H + d0);
                float x1, x2;
                x1 = acc[f][g][0]; x2 = acc[f][g + 4][0];
                acc[f][g][0]     = x1 * c0.x - x2 * s0.x;
                acc[f][g + 4][0] = x2 * c0.x + x1 * s0.x;
                x1 = acc[f][g][1]; x2 = acc[f][g + 4][1];
                acc[f][g][1]     = x1 * c0.y - x2 * s0.y;
                acc[f][g + 4][1] = x2 * c0.y + x1 * s0.y;
                x1 = acc[f][g][2]; x2 = acc[f][g + 4][2];
                acc[f][g][2]     = x1 * c1.x - x2 * s1.x;
                acc[f][g + 4][2] = x2 * c1.x + x1 * s1.x;
                x1 = acc[f][g][3]; x2 = acc[f][g + 4][3];
                acc[f][g][3]     = x1 * c1.y - x2 * s1.y;
                acc[f][g + 4][3] = x2 * c1.y + x1 * s1.y;
            }
        }
    }

    // split + store
    #pragma unroll
    for (int f = 0; f < 4; f++) {
        int row = m0 + wm * 64 + f * 16 + r;
        #pragma unroll
        for (int g = 0; g < 8; g++) {
            int col = cbase + g * 8 + c * 2;
            size_t o0 = (size_t)row * HIDDEN + col;
            size_t o1 = (size_t)(row + 8) * HIDDEN + col;
            split2_store(dh + o0, dl + o0, acc[f][g][0], acc[f][g][1]);
            split2_store(dh + o1, dl + o1, acc[f][g][2], acc[f][g][3]);
        }
    }
}

// ---------------------------------------------------------------------------
// fp16 3-pass compensated flash attention (causal), double-buffered k/v,
// static-shift softmax p = exp(s/16 - 4) (shift cancels in 1/l normalize).
// ---------------------------------------------------------------------------
#define AQ 64
#define AKT 32
#define H_QH 0
#define H_QL 16384
#define H_KH 32768               // stage 0; stage 1 = +KV_STG_H
#define H_KL 40960
#define H_VH 49152
#define H_VL 57344
#define KV_STG_H 32768
#define KV_STG_B 65536
#define H_PH 98304
#define H_PL 102400
#define F_PS 53248               // FLOAT units
#define ATT_SMEM  214528

__global__ __launch_bounds__(256, 1) void attn_h(
    const __half* __restrict__ qhg, const __half* __restrict__ qlg,
    const __half* __restrict__ khg, const __half* __restrict__ klg,
    const __half* __restrict__ vhg, const __half* __restrict__ vlg,
    __half* __restrict__ outp)
{
    extern __shared__ char sm[];
    __half* hp = (__half*)sm;
    float*  fpm = (float*)sm;
    const uint32_t sb = smem_u32(sm);

    const int tid = threadIdx.x, lane = tid & 31, w = tid >> 5;
    const int qt = 15 - blockIdx.x;
    const int bh = blockIdx.y;
    const int b = bh >> 4, h = bh & 15;
    const int t0 = b * SEQ + qt * AQ;
    const int wq = w & 3, wk = w >> 2;
    const int cL = lane & 3;
    const int rL = lane >> 2;
    const int rA = wq * 16 + rL;
    const int hoff = h * HD;
    const int ktmax = 2 * qt + 1;

    // ---- q tile via cp.async ----
    #pragma unroll
    for (int i = 0; i < 16; i++) {
        const __half* srcb = (i < 8) ? qhg : qlg;
        const uint32_t hbase = (i < 8) ? H_QH : H_QL;
        int rem = tid + 256 * (i & 7);
        int row = rem >> 5, ch = rem & 31;
        cp16(sb + 2 * (hbase + row * 256 + ((ch ^ (row & 7)) << 3)),
             srcb + (size_t)(t0 + row) * HIDDEN + hoff + ch * 8);
    }
    CP_COMMIT();
    // ---- k/v tile 0 into stage 0 ----
    {
        const int tk = b * SEQ;
        #pragma unroll
        for (int i = 0; i < 16; i++) {
            const __half* srcb = (i < 4) ? khg : (i < 8) ? klg : (i < 12) ? vhg : vlg;
            const uint32_t hbase = (i < 4) ? H_KH : (i < 8) ? H_KL : (i < 12) ? H_VH : H_VL;
            int rem = tid + 256 * (i & 3);
            int row = rem >> 5, ch = rem & 31;
            cp16(sb + 2 * (hbase + row * 256 + ((ch ^ (row & 7)) << 3)),
                 srcb + (size_t)(tk + row) * HIDDEN + hoff + ch * 8);
        }
        CP_COMMIT();
    }

    float o[16][4];
    #pragma unroll
    for (int g = 0; g < 16; g++)
        #pragma unroll
        for (int r = 0; r < 4; r++) o[g][r] = 0.f;
    float lsum0 = 0.f, lsum1 = 0.f;

    const int arow  = wq * 16 + (lane & 15);
    const int krow  = wk * 16 + ((lane & 7) | ((lane >> 4) << 3));
    const int vk    = lane & 15;
    const int acs   = lane >> 4;
    const int bcs   = (lane >> 3) & 1;
    const uint32_t qhB = sb + 2 * (H_QH + arow * 256);
    const uint32_t qlB = sb + 2 * (H_QL + arow * 256);
    const uint32_t khB = sb + 2 * (H_KH + krow * 256);
    const uint32_t klB = sb + 2 * (H_KL + krow * 256);
    const uint32_t phB = sb + 2 * (H_PH + arow * 64);
    const uint32_t plB = sb + 2 * (H_PL + arow * 64);
    const int arow7 = arow & 7, krow7 = krow & 7;

    for (int kt = 0; kt <= ktmax; kt++) {
        CP_WAIT0();
        __syncthreads();

        if (kt < ktmax) {
            const int tk = b * SEQ + (kt + 1) * AKT;
            const uint32_t stg = ((kt + 1) & 1) ? (uint32_t)KV_STG_B : 0u;
            #pragma unroll
            for (int i = 0; i < 16; i++) {
                const __half* srcb = (i < 4) ? khg : (i < 8) ? klg : (i < 12) ? vhg : vlg;
                const uint32_t hbase = (i < 4) ? H_KH : (i < 8) ? H_KL : (i < 12) ? H_VH : H_VL;
                int rem = tid + 256 * (i & 3);
                int row = rem >> 5, ch = rem & 31;
                cp16(stg + sb + 2 * (hbase + row * 256 + ((ch ^ (row & 7)) << 3)),
                     srcb + (size_t)(tk + row) * HIDDEN + hoff + ch * 8);
            }
            CP_COMMIT();
        }

        const uint32_t stgc = (kt & 1) ? (uint32_t)KV_STG_B : 0u;

        float sacc[2][4];
        #pragma unroll
        for (int g = 0; g < 2; g++)
            #pragma unroll
            for (int r = 0; r < 4; r++) sacc[g][r] = 0.f;

        #pragma unroll
        for (int s = 0; s < 16; s++) {
            unsigned ah[4], al2[4], bh2[4], bl2[4];
            uint32_t ac = (uint32_t)(((2 * s + acs) ^ arow7) << 4);
            uint32_t bc = (uint32_t)(((2 * s + bcs) ^ krow7) << 4);
            ldsm4(ah, qhB + ac);
            ldsm4(al2, qlB + ac);
            ldsm4(bh2, khB + stgc + bc);
            ldsm4(bl2, klB + stgc + bc);
            #pragma unroll
            for (int g = 0; g < 2; g++) {
                mma_f16(sacc[g], ah,  &bh2[2 * g]);
                mma_f16(sacc[g], al2, &bh2[2 * g]);
                mma_f16(sacc[g], ah,  &bl2[2 * g]);
            }
        }

        if (kt >= 2 * qt) {
            #pragma unroll
            for (int g = 0; g < 2; g++)
                #pragma unroll
                for (int r = 0; r < 4; r++) {
                    int col = kt * AKT + wk * 16 + g * 8 + 2 * cL + (r & 1);
                    int row = qt * AQ + rA + 8 * (r >> 1);
                    if (col > row) sacc[g][r] = -1e30f;
                }
        }

        // ---- p = exp(s/16 - 4); accumulate l; split-store to smem ----
        #pragma unroll
        for (int g = 0; g < 2; g++) {
            float p0 = __expf(sacc[g][0] * 0.0625f - 4.0f);
            float p1 = __expf(sacc[g][1] * 0.0625f - 4.0f);
            float p2 = __expf(sacc[g][2] * 0.0625f - 4.0f);
            float p3 = __expf(sacc[g][3] * 0.0625f - 4.0f);
            lsum0 += p0 + p1; lsum1 += p2 + p3;
            __half2 h01 = __floats2half2_rn(p0, p1);
            __half2 h23 = __floats2half2_rn(p2, p3);
            __half2 l01 = __floats2half2_rn(p0 - __low2float(h01), p1 - __high2float(h01));
            __half2 l23 = __floats2half2_rn(p2 - __low2float(h23), p3 - __high2float(h23));
            int pc = wk * 2 + g;
            uint32_t o0 = H_PH + rA * 64 + ((pc ^ (rA & 7)) << 3) + 2 * cL;
            uint32_t o1 = H_PH + (rA + 8) * 64 + ((pc ^ (rA & 7)) << 3) + 2 * cL;
            *(__half2*)&hp[o0] = h01;
            *(__half2*)&hp[o1] = h23;
            *(__half2*)&hp[o0 + (H_PL - H_PH)] = l01;
            *(__half2*)&hp[o1 + (H_PL - H_PH)] = l23;
        }
        __syncthreads();

        // ---- PV ----
        #pragma unroll
        for (int s = 0; s < 2; s++) {
            unsigned pa[4], pl4[4];
            uint32_t pc = (uint32_t)(((2 * s + acs) ^ arow7) << 4);
            ldsm4(pa, phB + pc);
            ldsm4(pl4, plB + pc);
            const uint32_t vrow = s * 16 + vk;
            const uint32_t vhBs = sb + stgc + 2 * (H_VH + vrow * 256);
            const uint32_t vlBs = sb + stgc + 2 * (H_VL + vrow * 256);
            const int vr7 = vrow & 7;
            #pragma unroll
            for (int G = 0; G < 8; G++) {
                unsigned vh4[4], vl4[4];
                uint32_t vc = (uint32_t)((((wk * 16 + 2 * G + acs)) ^ vr7) << 4);
                ldsm4t(vh4, vhBs + vc);
                ldsm4t(vl4, vlBs + vc);
                int gg = 2 * G;
                mma_f16(o[gg],     pa,  &vh4[0]);
                mma_f16(o[gg],     pl4, &vh4[0]);
                mma_f16(o[gg],     pa,  &vl4[0]);
                mma_f16(o[gg + 1], pa,  &vh4[2]);
                mma_f16(o[gg + 1], pl4, &vh4[2]);
                mma_f16(o[gg + 1], pa,  &vl4[2]);
            }
        }
    }

    // ---- final l reduction + normalize + store ----
    lsum0 += __shfl_xor_sync(0xffffffffu, lsum0, 1);
    lsum0 += __shfl_xor_sync(0xffffffffu, lsum0, 2);
    lsum1 += __shfl_xor_sync(0xffffffffu, lsum1, 1);
    lsum1 += __shfl_xor_sync(0xffffffffu, lsum1, 2);
    __syncthreads();
    if (cL == 0) {
        fpm[F_PS + wk * 64 + rA]     = lsum0;
        fpm[F_PS + wk * 64 + rA + 8] = lsum1;
    }
    __syncthreads();
    const float il0 = 1.0f / (fpm[F_PS + rA]     + fpm[F_PS + 64 + rA]);
    const float il1 = 1.0f / (fpm[F_PS + rA + 8] + fpm[F_PS + 64 + rA + 8]);
    #pragma unroll
    for (int g = 0; g < 16; g++) {
        int col = h * HD + wk * 128 + g * 8 + 2 * cL;
        *(__half2*)(outp + (size_t)(t0 + rA) * HIDDEN + col) =
            __floats2half2_rn(o[g][0] * il0, o[g][1] * il0);
        *(__half2*)(outp + (size_t)(t0 + rA + 8) * HIDDEN + col) =
            __floats2half2_rn(o[g][2] * il1, o[g][3] * il1);
    }
}

// ---------------------------------------------------------------------------
// launch
// ---------------------------------------------------------------------------
extern "C" void kernel_launch(void* const* d_in, const int* in_sizes, int n_in,
                              void* d_out, int out_size)
{
    const float* hidden = (const float*)d_in[0];
    const float* w_qkv  = (const float*)d_in[1];
    const float* w_o    = (const float*)d_in[2];
    const float* cosp   = (const float*)d_in[3];
    const float* sinp   = (const float*)d_in[4];
    // d_in[5..8] (caches, slots, batch_size) unused: cache write+gather is identity.

    __half* at16; cudaGetSymbolAddress((void**)&at16, g_attn16);
    __half* h16;  cudaGetSymbolAddress((void**)&h16,  g_hid16);
    __half* wq16; cudaGetSymbolAddress((void**)&wq16, g_wq16);
    __half* wo16; cudaGetSymbolAddress((void**)&wo16, g_wo16);
    __half *qh, *ql, *kh, *kl, *vh, *vl;
    cudaGetSymbolAddress((void**)&qh, g_qh);
    cudaGetSymbolAddress((void**)&ql, g_ql);
    cudaGetSymbolAddress((void**)&kh, g_kh);
    cudaGetSymbolAddress((void**)&kl, g_kl);
    cudaGetSymbolAddress((void**)&vh, g_vh);
    cudaGetSymbolAddress((void**)&vl, g_vl);

    cudaFuncSetAttribute(gemm_h,   cudaFuncAttributeMaxDynamicSharedMemorySize, GEMM_SMEM);
    cudaFuncSetAttribute(gemm_qkv, cudaFuncAttributeMaxDynamicSharedMemorySize, GEMM_SMEM);
    cudaFuncSetAttribute(attn_h,   cudaFuncAttributeMaxDynamicSharedMemorySize, ATT_SMEM);

    // 0) fp16 conversion pre-pass (single launch, three segments)
    {
        size_t total = F2H_N0 + F2H_N1 + F2H_N2;
        f2h_all<<<(unsigned)((total + 255) / 256), 256>>>(
            hidden, h16, w_qkv, wq16, w_o, wo16);
    }
    // 1) qkv GEMM with fused RoPE + hi/lo split epilogue (prep eliminated)
    {
        dim3 grid(QKV_W / GTILE_N, T_TOK / GTILE_M);   // (96, 64)
        gemm_qkv<<<grid, 128, GEMM_SMEM>>>(h16, wq16, cosp, sinp,
                                           qh, ql, kh, kl, vh, vl);
    }
    // 2) fp16 static-shift-softmax flash attention (double-buffered) -> fp16
    {
        dim3 grid(SEQ / AQ, BATCH * NHEAD);
        attn_h<<<grid, 256, ATT_SMEM>>>(qh, ql, kh, kl, vh, vl, at16);
    }
    // 3) out = attn @ w_o^T
    {
        dim3 grid(HIDDEN / GTILE_N, T_TOK / GTILE_M);  // (32, 64)
        gemm_h<<<grid, 128, GEMM_SMEM>>>(at16, wo16, (float*)d_out, T_TOK, HIDDEN, HIDDEN);
    }
}